// round 15
// baseline (speedup 1.0000x reference)
#include <cuda_runtime.h>
#include <cuda_fp16.h>
#include <stdint.h>
#include <stddef.h>

#define Bsz 64
#define Ssz 128
#define Tsz 64
#define Vsz 10000
#define Esz 128
#define Hsz 256
#define VPAD 10112            // V padded to multiple of 128

// ---------------- device scratch (no dynamic allocation allowed) ----------------
__device__ float g_xW[Bsz * Ssz * 2048];
__device__ float g_enc[Bsz * Ssz * 2 * Hsz];
__device__ float g_b1c[2048];
__device__ float g_b2c[2048];
__device__ float g_WhhT4[4 * 256 * 1024];
__device__ float g_dWT4[640 * 1024];
__device__ float g_h[2][2 * Bsz * Hsz];             // double-buffered h state
__device__ float g_hid[Bsz * Hsz];
__device__ float g_xin[Bsz * 640];
__device__ float g_hc[4096 * 768];                  // fp32 [h,ctx] (argmax fallback)
__device__ float g_scg[Bsz * 128];                  // attention scores exchange
__device__ float g_ctxp[Bsz * 512];                 // helper partial context

// barrier state (zero-initialized; generation-based, self-resetting, replay-safe)
__device__ int g_bcnt[8192];
__device__ int g_bgen[8192];

// fp16 buffers
__device__ __half g_Ah[8192 * 512];
__device__ __half g_hcH[4096 * 768];                // fp16 [h,ctx]; tail zeroed
__device__ __half g_encWaH[8192 * 256];             // fp16 enc@Wa2.T
__device__ __half g_Wa1TH[256 * 256];               // fp16 Wa1 transposed
__device__ __half g_B1hi[2048 * 128], g_B1lo[2048 * 128];
__device__ __half g_B2hi[2048 * 512], g_B2lo[2048 * 512];
__device__ __half g_BWahi[256 * 512], g_BWalo[256 * 512];
__device__ __half g_Bfchi[VPAD * 768], g_Bfclo[VPAD * 768];

// ---------------- fast math helpers ----------------
__device__ __forceinline__ float sigf(float x) {
    return __fdividef(1.f, 1.f + __expf(-x));
}
__device__ __forceinline__ float tanf_(float x) {
    x = fminf(fmaxf(x, -15.f), 15.f);
    float e = __expf(2.f * x);
    return __fdividef(e - 1.f, e + 1.f);
}

// ---------------- release/acquire barrier primitives (no full fences) ----------------
__device__ __forceinline__ int ld_acq(const int* p) {
    int v;
    asm volatile("ld.acquire.gpu.b32 %0, [%1];" : "=r"(v) : "l"(p) : "memory");
    return v;
}
__device__ __forceinline__ void st_rel(int* p, int v) {
    asm volatile("st.release.gpu.b32 [%0], %1;" :: "l"(p), "r"(v) : "memory");
}
__device__ __forceinline__ void st_rlx(int* p, int v) {
    asm volatile("st.relaxed.gpu.b32 [%0], %1;" :: "l"(p), "r"(v) : "memory");
}
__device__ __forceinline__ int atom_add_ar(int* p, int v) {
    int old;
    asm volatile("atom.acq_rel.gpu.add.s32 %0, [%1], %2;"
                 : "=r"(old) : "l"(p), "r"(v) : "memory");
    return old;
}

// single-level barrier: nb arrivals on group grp (LSTM grp 0..15; pairs grp 64+b)
__device__ __forceinline__ void group_barrier(int grp, int nb) {
    __syncthreads();
    if (threadIdx.x == 0) {
        int* cnt = g_bcnt + grp * 32;
        int* gen = g_bgen + grp * 32;
        int g0 = ld_acq(gen);
        if (atom_add_ar(cnt, 1) == nb - 1) {
            st_rlx(cnt, 0);
            st_rel(gen, g0 + 1);
        } else {
            while (ld_acq(gen) == g0) { }
        }
    }
    __syncthreads();
}

// two-level barrier for the 128-block decoder: 8 leaves x 16 + top of 8
#define DECB 1280
__device__ __forceinline__ void dec_barrier(int bid) {
    __syncthreads();
    if (threadIdx.x == 0) {
        int leaf = bid >> 4;
        int* lc  = g_bcnt + DECB + leaf * 32;
        int* tc  = g_bcnt + DECB + 8 * 32;
        int* gen = g_bgen + DECB;
        int g0 = ld_acq(gen);
        if (atom_add_ar(lc, 1) == 15) {
            if (atom_add_ar(tc, 1) == 7) {
#pragma unroll
                for (int l = 0; l < 8; l++) st_rlx(g_bcnt + DECB + l * 32, 0);
                st_rlx(tc, 0);
                st_rel(gen, g0 + 1);
            } else {
                while (ld_acq(gen) == g0) { }
            }
        } else {
            while (ld_acq(gen) == g0) { }
        }
    }
    __syncthreads();
}

// ---------------- warp-level fp16 MMA + ldmatrix + cp.async (sm_103-legal) ----------------
__device__ __forceinline__ void mma16816(float* c, const uint32_t* a, const uint32_t* b) {
    asm volatile(
        "mma.sync.aligned.m16n8k16.row.col.f32.f16.f16.f32 "
        "{%0,%1,%2,%3}, {%4,%5,%6,%7}, {%8,%9}, {%0,%1,%2,%3};"
        : "+f"(c[0]), "+f"(c[1]), "+f"(c[2]), "+f"(c[3])
        : "r"(a[0]), "r"(a[1]), "r"(a[2]), "r"(a[3]), "r"(b[0]), "r"(b[1]));
}
__device__ __forceinline__ void ldsm4(uint32_t* r, uint32_t a) {
    asm volatile("ldmatrix.sync.aligned.m8n8.x4.shared.b16 {%0,%1,%2,%3}, [%4];"
                 : "=r"(r[0]), "=r"(r[1]), "=r"(r[2]), "=r"(r[3]) : "r"(a));
}
__device__ __forceinline__ void cp16(uint32_t s, const void* g) {
    asm volatile("cp.async.cg.shared.global [%0], [%1], 16;" :: "r"(s), "l"(g));
}
__device__ __forceinline__ void cp_commit() {
    asm volatile("cp.async.commit_group;" ::: "memory");
}
template <int N>
__device__ __forceinline__ void cp_waitg() {
    asm volatile("cp.async.wait_group %0;" :: "n"(N) : "memory");
}

#define LDSW 72                       // smem row stride (64 data + 8 pad) in fp16
#define TILE_E (128 * LDSW)           // elems per tile buffer
#define STAGE_B (3 * TILE_E * 2)      // bytes per stage (A, Bhi, Blo)
#define TCSM (2 * STAGE_B)            // 110592 bytes, 2 stages

// ---------------- fp16 2-term split tensor-core GEMM, double-buffered ----------------
// C = A[M,K] @ (Bhi+Blo)[N,K]^T + bias.  mode 0: fp32 C. mode 1: fp32 scatter.
// mode 2: fp16 C (half* reinterpreted).
__global__ __launch_bounds__(256, 2) void gemm_tc(
    const __half* __restrict__ A,
    const __half* __restrict__ Bhi, const __half* __restrict__ Blo,
    const float* __restrict__ bias, float* __restrict__ C,
    int Mreal, int Nreal, int K, int mode)
{
    extern __shared__ __half sm[];
    uint32_t s0 = (uint32_t)__cvta_generic_to_shared(sm);

    int tid = threadIdx.x;
    int warp = tid >> 5, lane = tid & 31;
    int m0 = blockIdx.x * 128, n0 = blockIdx.y * 128;
    int mw = (warp >> 1) * 32, nw = (warp & 1) * 64;

    float acc[2][8][4];
#pragma unroll
    for (int i = 0; i < 2; i++)
#pragma unroll
        for (int j = 0; j < 8; j++)
#pragma unroll
            for (int q = 0; q < 4; q++) acc[i][j][q] = 0.f;

    int ar = lane >> 2;
    int acq = (lane & 3) * 2;

    uint32_t aoffB = (uint32_t)(((mw + (lane & 15)) * LDSW + (lane >> 4) * 8) * 2);
    int bq = lane >> 3, br = lane & 7;
    uint32_t boffB[4];
#pragma unroll
    for (int p = 0; p < 4; p++)
        boffB[p] = (uint32_t)(((nw + (2 * p + (bq >> 1)) * 8 + br) * LDSW + (bq & 1) * 8) * 2);
    const uint32_t MT_OFF = 16 * LDSW * 2;

    int srow = tid >> 3, sc8 = (tid & 7) * 8;
    int nc = K >> 6;

    auto load_chunk = [&](int c, int stg) {
        uint32_t base = s0 + (uint32_t)stg * STAGE_B;
#pragma unroll
        for (int i = 0; i < 4; i++) {
            int row = srow + i * 32;
            uint32_t so2 = (uint32_t)((row * LDSW + sc8) * 2);
            size_t ga = (size_t)(m0 + row) * K + c * 64 + sc8;
            size_t gb = (size_t)(n0 + row) * K + c * 64 + sc8;
            cp16(base + so2, A + ga);
            cp16(base + TILE_E * 2 + so2, Bhi + gb);
            cp16(base + 2 * TILE_E * 2 + so2, Blo + gb);
        }
        cp_commit();
    };

    load_chunk(0, 0);
    for (int c = 0; c < nc; c++) {
        int stg = c & 1;
        if (c + 1 < nc) {
            load_chunk(c + 1, stg ^ 1);
            cp_waitg<1>();
        } else {
            cp_waitg<0>();
        }
        __syncthreads();
        uint32_t sA32 = s0 + (uint32_t)stg * STAGE_B;
        uint32_t sBh32 = sA32 + TILE_E * 2;
        uint32_t sBl32 = sA32 + 2 * TILE_E * 2;
#pragma unroll
        for (int k16 = 0; k16 < 4; k16++) {
            uint32_t kby = (uint32_t)k16 * 32;
            uint32_t ah[2][4], bf[4][4];
            ldsm4(ah[0], sA32 + aoffB + kby);
            ldsm4(ah[1], sA32 + aoffB + MT_OFF + kby);
#pragma unroll
            for (int p = 0; p < 4; p++) ldsm4(bf[p], sBh32 + boffB[p] + kby);
#pragma unroll
            for (int mt = 0; mt < 2; mt++)
#pragma unroll
                for (int p = 0; p < 4; p++) {
                    mma16816(acc[mt][2 * p],     ah[mt], &bf[p][0]);   // A*Bhi
                    mma16816(acc[mt][2 * p + 1], ah[mt], &bf[p][2]);
                }
#pragma unroll
            for (int p = 0; p < 4; p++) ldsm4(bf[p], sBl32 + boffB[p] + kby);
#pragma unroll
            for (int mt = 0; mt < 2; mt++)
#pragma unroll
                for (int p = 0; p < 4; p++) {
                    mma16816(acc[mt][2 * p],     ah[mt], &bf[p][0]);   // A*Blo
                    mma16816(acc[mt][2 * p + 1], ah[mt], &bf[p][2]);
                }
        }
        __syncthreads();
    }

#pragma unroll
    for (int mt = 0; mt < 2; mt++) {
#pragma unroll
        for (int half = 0; half < 2; half++) {
            int m = m0 + mw + mt * 16 + ar + half * 8;
            if (m >= Mreal) continue;
#pragma unroll
            for (int nt = 0; nt < 8; nt++) {
                int col = n0 + nw + nt * 8 + acq;
                float v0 = acc[mt][nt][half * 2 + 0] + (bias ? bias[col] : 0.f);
                float v1 = acc[mt][nt][half * 2 + 1]
                         + ((bias && col + 1 < Nreal) ? bias[col + 1] : 0.f);
                if (mode == 2) {
                    __half* crow = ((__half*)C) + (size_t)m * Nreal;
                    if (col < Nreal)     crow[col]     = __float2half(v0);
                    if (col + 1 < Nreal) crow[col + 1] = __float2half(v1);
                } else {
                    float* crow;
                    if (mode == 1) {
                        int b = m & 63, st = m >> 6;
                        crow = C + ((size_t)b * Tsz + st + 1) * (size_t)Nreal;
                    } else {
                        crow = C + (size_t)m * Nreal;
                    }
                    if (col < Nreal)     crow[col]     = v0;
                    if (col + 1 < Nreal) crow[col + 1] = v1;
                }
            }
        }
    }
}

// ---------------- fused embed gather + fp16 convert (layer-1 A) ----------------
__global__ void emb_half(const int* __restrict__ src, const float* __restrict__ emb,
                         __half* __restrict__ dst) {
    int row = blockIdx.x, t = threadIdx.x;
    dst[(size_t)row * Esz + t] = __float2half(emb[(size_t)src[row] * Esz + t]);
}

// ---------------- one fused prep kernel: transposes + bias + weight splits ----------------
__global__ void prep_fused(
    const float* __restrict__ Wa,
    const float* __restrict__ w1f, const float* __restrict__ w1b,
    const float* __restrict__ w2f, const float* __restrict__ w2b,
    const float* __restrict__ dW,
    const float* __restrict__ b1f, const float* __restrict__ b1b,
    const float* __restrict__ b2f, const float* __restrict__ b2b,
    const float* __restrict__ e1f, const float* __restrict__ e1b,
    const float* __restrict__ e2f, const float* __restrict__ e2b,
    const float* __restrict__ Wfc,
    __half* __restrict__ Wa1TH, float* __restrict__ WhhT4,
    float* __restrict__ dWT4, float* __restrict__ b1c, float* __restrict__ b2c,
    float* __restrict__ hcTail, __half* __restrict__ hcHTail,
    __half* __restrict__ B1hi, __half* __restrict__ B1lo,
    __half* __restrict__ B2hi, __half* __restrict__ B2lo,
    __half* __restrict__ BWahi, __half* __restrict__ BWalo,
    __half* __restrict__ Bfchi, __half* __restrict__ Bfclo)
{
    int i = blockIdx.x * 256 + threadIdx.x;
    if (i < 65536) {                         // Wa1T (fp16)
        int r = i & 255, k = i >> 8;
        Wa1TH[k * 256 + r] = __float2half(Wa[r * 768 + k]);
        return;
    }
    i -= 65536;
    if (i < 4 * 262144) {                    // 4x Whh tpose4
        int d = i >> 18, j = i & 262143;
        int r = j & 1023, k = j >> 10;
        const float* s = (d == 0) ? w1f : (d == 1) ? w1b : (d == 2) ? w2f : w2b;
        WhhT4[(size_t)d * 262144 + (size_t)(k >> 2) * 4096 + r * 4 + (k & 3)] = s[r * 256 + k];
        return;
    }
    i -= 4 * 262144;
    if (i < 655360) {                        // dWih tpose4
        int r = i & 1023, k = i >> 10;
        dWT4[(size_t)(k >> 2) * 4096 + r * 4 + (k & 3)] = dW[r * 640 + k];
        return;
    }
    i -= 655360;
    if (i < 1024) { b1c[i] = b1f[i]; b1c[1024 + i] = b1b[i]; return; }
    i -= 1024;
    if (i < 1024) { b2c[i] = b2f[i]; b2c[1024 + i] = b2b[i]; return; }
    i -= 1024;
    if (i < 49152) { hcTail[i] = 0.f; return; }
    i -= 49152;
    if (i < 49152) { hcHTail[i] = __float2half(0.f); return; }
    i -= 49152;
    // ---- weight fp16 hi/lo splits ----
    float x; size_t di; __half* hi; __half* lo;
    if (i < 131072) {
        x = e1f[i]; di = i; hi = B1hi; lo = B1lo;
    } else if ((i -= 131072) < 131072) {
        x = e1b[i]; di = (size_t)131072 + i; hi = B1hi; lo = B1lo;
    } else if ((i -= 131072) < 524288) {
        x = e2f[i]; di = i; hi = B2hi; lo = B2lo;
    } else if ((i -= 524288) < 524288) {
        x = e2b[i]; di = (size_t)524288 + i; hi = B2hi; lo = B2lo;
    } else if ((i -= 524288) < 131072) {
        int r = i >> 9, c = i & 511;
        x = Wa[(size_t)r * 768 + 256 + c]; di = i; hi = BWahi; lo = BWalo;
    } else if ((i -= 131072) < VPAD * 768) {
        int r = i / 768, c = i - r * 768;
        x = (r < Vsz) ? Wfc[(size_t)r * 768 + c] : 0.f;
        di = i; hi = Bfchi; lo = Bfclo;
    } else return;
    __half h = __float2half(x);
    hi[di] = h;
    lo[di] = __float2half(x - __half2float(h));
}

// ---------------- weight-stationary persistent LSTM layer ----------------
// grid 256: jc(16) + 16*bg(8) + 128*d(2); 2 CTAs/SM for latency hiding.
// Each block: 16 j-values, 8 batches; weight slice 64KB smem.
#define LSTM_DSM (65536 + 8192)
__global__ __launch_bounds__(256, 2) void lstm_layer(
    const float* __restrict__ xW, const float* __restrict__ WhhT4,
    float* __restrict__ hbuf, float* __restrict__ out, __half* __restrict__ outh)
{
    extern __shared__ char dsm[];
    float4* ws  = (float4*)dsm;                  // [64 k4][64 gj]
    float4* hsm = (float4*)(dsm + 65536);        // [8 bi][64 k4]
    __shared__ float part[4][16][8];

    int bid = blockIdx.x;
    int jc = bid & 15, bg = (bid >> 4) & 7, d = bid >> 7;
    int grp = d * 8 + bg;
    int tid = threadIdx.x;
    float* h0 = hbuf;
    float* h1 = hbuf + 2 * Bsz * Hsz;

    const float4* W4 = (const float4*)(WhhT4 + (size_t)d * 262144);
    for (int idx = tid; idx < 64 * 64; idx += 256) {
        int k4 = idx >> 6, gjl = idx & 63;
        int g = gjl >> 4, j = gjl & 15;
        ws[idx] = W4[(size_t)k4 * 1024 + g * 256 + jc * 16 + j];
    }
    // zero h0 slice (16 blocks redundantly write same zeros: idempotent)
    for (int idx = tid; idx < 2048; idx += 256) {
        int bi = idx >> 8, k = idx & 255;
        h0[(d * 64 + bg * 8 + bi) * 256 + k] = 0.f;
    }
    int j2 = tid >> 3, bl = tid & 7;            // finalize map (tid<128)
    int jg = jc * 16 + j2;
    int b  = bg * 8 + bl;
    float creg = 0.f;
    int gj = tid >> 2, pr = tid & 3;            // compute map: 2 batches/thread

    // prefetch step-0 gate inputs (finalize threads only)
    float xg0 = 0.f, xg1 = 0.f, xg2 = 0.f, xg3 = 0.f;
    if (tid < 128) {
        int s0i = (d == 0) ? 0 : (Ssz - 1);
        const float* xr = xW + (size_t)(b * Ssz + s0i) * 2048 + d * 1024;
        xg0 = xr[jg]; xg1 = xr[256 + jg]; xg2 = xr[512 + jg]; xg3 = xr[768 + jg];
    }
    group_barrier(grp, 16);

    for (int t = 0; t < Ssz; t++) {
        const float* hprev = (t & 1) ? h1 : h0;
        float* hnext = (t & 1) ? h0 : h1;
        int s = (d == 0) ? t : (Ssz - 1 - t);
        for (int idx = tid; idx < 512; idx += 256) {
            int bi = idx >> 6, k4 = idx & 63;
            hsm[idx] = __ldcg((const float4*)(hprev +
                           (size_t)(d * 64 + bg * 8 + bi) * 256) + k4);
        }
        __syncthreads();
        float a0 = 0.f, a1 = 0.f;
        const float4* hb0 = hsm + (pr * 2) * 64;
        const float4* hb1 = hsm + (pr * 2 + 1) * 64;
#pragma unroll 8
        for (int k4 = 0; k4 < 64; k4++) {
            float4 w = ws[k4 * 64 + gj];
            float4 x0 = hb0[k4], x1 = hb1[k4];
            a0 += w.x * x0.x + w.y * x0.y + w.z * x0.z + w.w * x0.w;
            a1 += w.x * x1.x + w.y * x1.y + w.z * x1.z + w.w * x1.w;
        }
        {
            int gg = gj >> 4, jj = gj & 15;
            part[gg][jj][pr * 2 + 0] = a0;
            part[gg][jj][pr * 2 + 1] = a1;
        }
        __syncthreads();
        if (tid < 128) {
            float gi = part[0][j2][bl] + xg0;
            float gf = part[1][j2][bl] + xg1;
            float g_ = part[2][j2][bl] + xg2;
            float go = part[3][j2][bl] + xg3;
            creg = sigf(gf) * creg + sigf(gi) * tanf_(g_);
            float h = sigf(go) * tanf_(creg);
            hnext[(d * 64 + b) * 256 + jg] = h;
            size_t oidx = (size_t)(b * Ssz + s) * 512 + d * 256 + jg;
            if (out) out[oidx] = h;
            outh[oidx] = __float2half(h);
            // prefetch next step's gate inputs before the barrier
            if (t + 1 < Ssz) {
                int sn = (d == 0) ? (t + 1) : (Ssz - 2 - t);
                const float* xr2 = xW + (size_t)(b * Ssz + sn) * 2048 + d * 1024;
                xg0 = xr2[jg]; xg1 = xr2[256 + jg];
                xg2 = xr2[512 + jg]; xg3 = xr2[768 + jg];
            }
        }
        group_barrier(grp, 16);
    }
}

// ---------------- persistent decoder: split phase A across block pairs ----------------
#define DEC_DSM (163840 + 20480)
__global__ __launch_bounds__(256) void decoder_all(
    const int* __restrict__ trg, const int* __restrict__ tfmask,
    const float* __restrict__ enc, const __half* __restrict__ encWaH,
    const __half* __restrict__ Wa1TH, const float* __restrict__ ba,
    const float* __restrict__ vvec, const float* __restrict__ dWT4,
    const float* __restrict__ db, const float* __restrict__ demb,
    const float* __restrict__ Wfc, const float* __restrict__ bfc,
    float* __restrict__ xin, float* __restrict__ hid,
    float* __restrict__ hc, __half* __restrict__ hcH,
    float* __restrict__ scg, float* __restrict__ ctxp)
{
    extern __shared__ char dsm[];
    float4* dws = (float4*)dsm;                   // [160 k4][64 gj]
    float4* xs4 = (float4*)(dsm + 163840);        // [8 b][160 k4]
    __shared__ float hsm_[256], hwa_[256], vs_[256], sc_[128];
    __shared__ float redm_, reds_;
    __shared__ int tok_;
    __shared__ float partB[4][16][8];
    __shared__ float ax_[768];
    __shared__ float abv_[256];
    __shared__ int abi_[256];

    int bid = blockIdx.x, tid = threadIdx.x;
    int jcB = bid & 15, bgB = bid >> 4;
    int b = bid & 63, sh = bid >> 6;              // pair role: sh=0 primary, 1 helper

    vs_[tid] = vvec[tid];
    {
        const float4* dW4 = (const float4*)dWT4;
        for (int i2 = tid; i2 < 160 * 64; i2 += 256) {
            int k4 = i2 >> 6, gj2 = i2 & 63;
            int g = gj2 >> 4, jj = gj2 & 15;
            dws[i2] = dW4[(size_t)k4 * 1024 + g * 256 + jcB * 16 + jj];
        }
    }
    dec_barrier(bid);

    for (int st = 0; st < Tsz - 1; st++) {
        // ===== phase A: pair (b, b+64), s-range split =====
        if (st == 0) hsm_[tid] = enc[((size_t)b * Ssz + (Ssz - 1)) * 512 + tid];
        else         hsm_[tid] = __ldcg(&hid[b * 256 + tid]);

        if (sh == 0) {
            if (st == 0) {
                if (tid == 0) tok_ = trg[b * Tsz];
            } else if (tfmask[st] != 0) {
                if (tid == 0) tok_ = trg[b * Tsz + st];
            } else {
                const float* hcp = hc + ((size_t)(st - 1) * Bsz + b) * 768;
                for (int i = tid; i < 768; i += 256) ax_[i] = __ldcg(&hcp[i]);
                __syncthreads();
                float best = -1e30f; int bix = 0;
                for (int v0 = tid; v0 < Vsz; v0 += 256) {
                    float s = bfc[v0];
                    const float* wr = Wfc + (size_t)v0 * 768;
                    for (int k = 0; k < 768; k++) s += ax_[k] * wr[k];
                    if (s > best) { best = s; bix = v0; }
                }
                abv_[tid] = best; abi_[tid] = bix;
                __syncthreads();
                for (int off = 128; off; off >>= 1) {
                    if (tid < off) {
                        if (abv_[tid + off] > abv_[tid] ||
                            (abv_[tid + off] == abv_[tid] && abi_[tid + off] < abi_[tid])) {
                            abv_[tid] = abv_[tid + off];
                            abi_[tid] = abi_[tid + off];
                        }
                    }
                    __syncthreads();
                }
                if (tid == 0) tok_ = abi_[0];
            }
        }
        __syncthreads();
        if (sh == 0 && tid < 128) xin[b * 640 + tid] = demb[(size_t)tok_ * 128 + tid];

        // hWa (both blocks, full, fp16 weights)
        {
            float acc = ba[tid];
#pragma unroll 16
            for (int k = 0; k < 256; k++)
                acc += hsm_[k] * __half2float(Wa1TH[k * 256 + tid]);
            hwa_[tid] = acc;
        }
        __syncthreads();

        // energies for own 64-s half -> global scores
        {
            int w = tid >> 5, l = tid & 31;
#pragma unroll
            for (int i = 0; i < 8; i++) {
                int s = sh * 64 + w * 8 + i;
                const __half* ep = encWaH + ((size_t)b * Ssz + s) * 256;
                float a2 = 0.f;
#pragma unroll
                for (int q = 0; q < 8; q++) {
                    int h = l + q * 32;
                    a2 += tanf_(hwa_[h] + __half2float(ep[h])) * vs_[h];
                }
#pragma unroll
                for (int o = 16; o; o >>= 1) a2 += __shfl_xor_sync(0xFFFFFFFFu, a2, o);
                if (l == 0) scg[b * 128 + s] = a2;
            }
        }
        group_barrier(64 + b, 2);                 // pair exchange: scores

        if (tid < 128) sc_[tid] = __ldcg(&scg[b * 128 + tid]);
        __syncthreads();
        if (tid < 32) {
            float m = fmaxf(fmaxf(sc_[tid], sc_[tid + 32]),
                            fmaxf(sc_[tid + 64], sc_[tid + 96]));
#pragma unroll
            for (int o = 16; o; o >>= 1) m = fmaxf(m, __shfl_xor_sync(0xFFFFFFFFu, m, o));
            if (tid == 0) redm_ = m;
        }
        __syncthreads();
        float mx = redm_;
        if (tid < 128) sc_[tid] = __expf(sc_[tid] - mx);
        __syncthreads();
        if (tid < 32) {
            float s_ = sc_[tid] + sc_[tid + 32] + sc_[tid + 64] + sc_[tid + 96];
#pragma unroll
            for (int o = 16; o; o >>= 1) s_ += __shfl_xor_sync(0xFFFFFFFFu, s_, o);
            if (tid == 0) reds_ = __fdividef(1.f, s_);
        }
        __syncthreads();
        {
            float inv = reds_;
            float c0 = 0.f, c1 = 0.f;
            const float* eb = enc + (size_t)b * Ssz * 512 + (size_t)sh * 64 * 512;
#pragma unroll 8
            for (int s = 0; s < 64; s++) {
                float a = sc_[sh * 64 + s] * inv;
                c0 += a * eb[s * 512 + tid];
                c1 += a * eb[s * 512 + 256 + tid];
            }
            if (sh == 1) {
                ctxp[b * 512 + tid]       = c0;
                ctxp[b * 512 + 256 + tid] = c1;
            }
            group_barrier(64 + b, 2);             // pair exchange: partial context
            if (sh == 0) {
                c0 += __ldcg(&ctxp[b * 512 + tid]);
                c1 += __ldcg(&ctxp[b * 512 + 256 + tid]);
                xin[b * 640 + 128 + tid] = c0;
                xin[b * 640 + 384 + tid] = c1;
                size_t hcb = ((size_t)st * Bsz + b) * 768;
                hc[hcb + 256 + tid] = c0;
                hc[hcb + 512 + tid] = c1;
                hcH[hcb + 256 + tid] = __float2half(c0);
                hcH[hcb + 512 + tid] = __float2half(c1);
            }
        }
        dec_barrier(bid);

        // ===== phase B: gates, all 128 blocks =====
        {
            for (int i2 = tid; i2 < 8 * 160; i2 += 256) {
                int bi = i2 / 160, k4 = i2 - bi * 160;
                xs4[i2] = __ldcg((const float4*)(xin +
                               (size_t)(bgB * 8 + bi) * 640) + k4);
            }
            __syncthreads();
            int g = tid >> 6, jj = (tid >> 2) & 15, bq = tid & 3;
            float s0 = 0.f, s1 = 0.f;
            const float4* xa = xs4 + (bq * 2) * 160;
            const float4* xb = xs4 + (bq * 2 + 1) * 160;
            const float4* wp = dws + (g * 16 + jj);
#pragma unroll 4
            for (int k4 = 0; k4 < 160; k4++) {
                float4 w = wp[k4 * 64];
                float4 xA = xa[k4], xB = xb[k4];
                s0 += w.x * xA.x + w.y * xA.y + w.z * xA.z + w.w * xA.w;
                s1 += w.x * xB.x + w.y * xB.y + w.z * xB.z + w.w * xB.w;
            }
            partB[g][jj][bq * 2]     = s0;
            partB[g][jj][bq * 2 + 1] = s1;
            __syncthreads();
            if (tid < 128) {
                int jjf = tid >> 3, blf = tid & 7;
                int jgf = jcB * 16 + jjf, bbf = bgB * 8 + blf;
                float gi = partB[0][jjf][blf] + db[jgf];
                float g2 = partB[2][jjf][blf] + db[512 + jgf];
                float go = partB[3][jjf][blf] + db[768 + jgf];
                float cc = sigf(gi) * tanf_(g2);
                float hh = sigf(go) * tanf_(cc);
                hid[bbf * 256 + jgf] = hh;
                size_t hci = ((size_t)st * Bsz + bbf) * 768 + jgf;
                hc[hci] = hh;
                hcH[hci] = __float2half(hh);
            }
        }
        dec_barrier(bid);
    }
}

__global__ void zero_t0(float* __restrict__ out) {
    int b = blockIdx.x;
    int v = blockIdx.y * 256 + threadIdx.x;
    if (v < Vsz) out[(size_t)b * Tsz * Vsz + v] = 0.f;
}

// ---------------- host launch ----------------
static float* symaddr(const void* sym) {
    void* p = nullptr;
    cudaGetSymbolAddress(&p, sym);
    return (float*)p;
}
static __half* symaddrh(const void* sym) {
    void* p = nullptr;
    cudaGetSymbolAddress(&p, sym);
    return (__half*)p;
}

extern "C" void kernel_launch(void* const* d_in, const int* in_sizes, int n_in,
                              void* d_out, int out_size) {
    const int*   src     = (const int*)d_in[0];
    const int*   trg     = (const int*)d_in[1];
    const int*   tfmask  = (const int*)d_in[2];
    const float* enc_emb = (const float*)d_in[3];
    const float* e1f_Wih = (const float*)d_in[4];
    const float* e1f_Whh = (const float*)d_in[5];
    const float* e1f_b   = (const float*)d_in[6];
    const float* e1b_Wih = (const float*)d_in[7];
    const float* e1b_Whh = (const float*)d_in[8];
    const float* e1b_b   = (const float*)d_in[9];
    const float* e2f_Wih = (const float*)d_in[10];
    const float* e2f_Whh = (const float*)d_in[11];
    const float* e2f_b   = (const float*)d_in[12];
    const float* e2b_Wih = (const float*)d_in[13];
    const float* e2b_Whh = (const float*)d_in[14];
    const float* e2b_b   = (const float*)d_in[15];
    const float* dec_emb = (const float*)d_in[16];
    const float* Wa      = (const float*)d_in[17];
    const float* ba      = (const float*)d_in[18];
    const float* vvec    = (const float*)d_in[19];
    const float* dWih    = (const float*)d_in[20];
    const float* db      = (const float*)d_in[21];
    const float* Wfc     = (const float*)d_in[22];
    const float* bfc     = (const float*)d_in[23];
    float* out = (float*)d_out;

    float* p_xW    = symaddr(g_xW);
    float* p_enc   = symaddr(g_enc);
    float* p_b1c   = symaddr(g_b1c);
    float* p_b2c   = symaddr(g_b2c);
    float* p_WhhT4 = symaddr(g_WhhT4);
    float* p_dWT4  = symaddr(g_dWT4);
    float* p_h     = symaddr(g_h);
    float* p_hid   = symaddr(g_hid);
    float* p_xin   = symaddr(g_xin);
    float* p_hc    = symaddr(g_hc);
    float* p_scg   = symaddr(g_scg);
    float* p_ctxp  = symaddr(g_ctxp);

    __half* p_Ah     = symaddrh(g_Ah);
    __half* p_hcH    = symaddrh(g_hcH);
    __half* p_encWaH = symaddrh(g_encWaH);
    __half* p_Wa1TH  = symaddrh(g_Wa1TH);
    __half* p_B1hi = symaddrh(g_B1hi), * p_B1lo = symaddrh(g_B1lo);
    __half* p_B2hi = symaddrh(g_B2hi), * p_B2lo = symaddrh(g_B2lo);
    __half* p_BWahi = symaddrh(g_BWahi), * p_BWalo = symaddrh(g_BWalo);
    __half* p_Bfchi = symaddrh(g_Bfchi), * p_Bfclo = symaddrh(g_Bfclo);

    cudaFuncSetAttribute(gemm_tc, cudaFuncAttributeMaxDynamicSharedMemorySize, TCSM);
    cudaFuncSetAttribute(lstm_layer, cudaFuncAttributeMaxDynamicSharedMemorySize, LSTM_DSM);
    cudaFuncSetAttribute(decoder_all, cudaFuncAttributeMaxDynamicSharedMemorySize, DEC_DSM);

    auto nb = [](int n) { return (n + 255) / 256; };

    // [1] fused prep
    const int PREP_N = 65536 + 4 * 262144 + 655360 + 1024 + 1024 + 49152 + 49152
                     + 131072 + 131072 + 524288 + 524288 + 131072 + VPAD * 768;
    prep_fused<<<nb(PREP_N), 256>>>(
        Wa, e1f_Whh, e1b_Whh, e2f_Whh, e2b_Whh, dWih,
        e1f_b, e1b_b, e2f_b, e2b_b,
        e1f_Wih, e1b_Wih, e2f_Wih, e2b_Wih, Wfc,
        p_Wa1TH, p_WhhT4, p_dWT4, p_b1c, p_b2c,
        p_hc + (size_t)4032 * 768, p_hcH + (size_t)4032 * 768,
        p_B1hi, p_B1lo, p_B2hi, p_B2lo, p_BWahi, p_BWalo, p_Bfchi, p_Bfclo);
    // [2] embed + fp16 convert fused
    emb_half<<<Bsz * Ssz, Esz>>>(src, enc_emb, p_Ah);
    // [3] layer-1 GEMM
    gemm_tc<<<dim3(64, 16), 256, TCSM>>>(p_Ah, p_B1hi, p_B1lo,
                                         p_b1c, p_xW, 8192, 2048, 128, 0);
    // [4] layer-1 recurrence (256 blocks, 2 CTAs/SM)
    lstm_layer<<<256, 256, LSTM_DSM>>>(p_xW, p_WhhT4, p_h, nullptr, p_Ah);
    // [5] layer-2 GEMM
    gemm_tc<<<dim3(64, 16), 256, TCSM>>>(p_Ah, p_B2hi, p_B2lo,
                                         p_b2c, p_xW, 8192, 2048, 512, 0);
    // [6] layer-2 recurrence
    lstm_layer<<<256, 256, LSTM_DSM>>>(p_xW, p_WhhT4 + 2 * 262144, p_h, p_enc, p_Ah);
    // [7] attention precompute GEMM -> fp16 encWa
    gemm_tc<<<dim3(64, 2), 256, TCSM>>>(p_Ah, p_BWahi, p_BWalo,
                                        nullptr, (float*)p_encWaH, 8192, 256, 512, 2);
    // [8] persistent decoder (pair-split phase A)
    decoder_all<<<128, 256, DEC_DSM>>>(trg, tfmask, p_enc, p_encWaH, p_Wa1TH, ba, vvec,
                                       p_dWT4, db, dec_emb, Wfc, bfc,
                                       p_xin, p_hid, p_hc, p_hcH, p_scg, p_ctxp);
    // [9] final projection (scatter into out)
    gemm_tc<<<dim3(32, 79), 256, TCSM>>>(p_hcH, p_Bfchi, p_Bfclo,
                                         bfc, out, 4032, Vsz, 768, 1);
    // [10] zero t=0 outputs
    zero_t0<<<dim3(Bsz, (Vsz + 255) / 256), 256>>>(out);
}

// round 16
// speedup vs baseline: 1.5794x; 1.5794x over previous
#include <cuda_runtime.h>
#include <cuda_fp16.h>
#include <stdint.h>
#include <stddef.h>

#define Bsz 64
#define Ssz 128
#define Tsz 64
#define Vsz 10000
#define Esz 128
#define Hsz 256
#define VPAD 10112            // V padded to multiple of 128

// ---------------- device scratch (no dynamic allocation allowed) ----------------
__device__ float g_xW[Bsz * Ssz * 2048];
__device__ float g_enc[Bsz * Ssz * 2 * Hsz];
__device__ float g_b1c[2048];
__device__ float g_b2c[2048];
__device__ float g_WhhT4[4 * 256 * 1024];
__device__ float g_dWT4[640 * 1024];
__device__ float g_h[2][2 * Bsz * Hsz];             // double-buffered h state
__device__ float g_hid[Bsz * Hsz];
__device__ float g_xin[Bsz * 640];
__device__ float g_hc[4096 * 768];                  // fp32 [h,ctx] (argmax fallback)
__device__ float g_scg[Bsz * 128];                  // attention scores exchange
__device__ float g_ctxp[Bsz * 512];                 // helper partial context

// barrier state (zero-initialized; generation-based, self-resetting, replay-safe)
__device__ int g_bcnt[8192];
__device__ int g_bgen[8192];

// fp16 buffers
__device__ __half g_Ah[8192 * 512];
__device__ __half g_hcH[4096 * 768];                // fp16 [h,ctx]; tail zeroed
__device__ __half g_encWaH[8192 * 256];             // fp16 enc@Wa2.T
__device__ __half g_Wa1TH[256 * 256];               // fp16 Wa1 transposed
__device__ __half g_B1hi[2048 * 128], g_B1lo[2048 * 128];
__device__ __half g_B2hi[2048 * 512], g_B2lo[2048 * 512];
__device__ __half g_BWahi[256 * 512], g_BWalo[256 * 512];
__device__ __half g_Bfchi[VPAD * 768], g_Bfclo[VPAD * 768];

// ---------------- fast math helpers ----------------
__device__ __forceinline__ float sigf(float x) {
    return __fdividef(1.f, 1.f + __expf(-x));
}
__device__ __forceinline__ float tanf_(float x) {
    x = fminf(fmaxf(x, -15.f), 15.f);
    float e = __expf(2.f * x);
    return __fdividef(e - 1.f, e + 1.f);
}

// ---------------- release/acquire barrier primitives (no full fences) ----------------
__device__ __forceinline__ int ld_acq(const int* p) {
    int v;
    asm volatile("ld.acquire.gpu.b32 %0, [%1];" : "=r"(v) : "l"(p) : "memory");
    return v;
}
__device__ __forceinline__ void st_rel(int* p, int v) {
    asm volatile("st.release.gpu.b32 [%0], %1;" :: "l"(p), "r"(v) : "memory");
}
__device__ __forceinline__ void st_rlx(int* p, int v) {
    asm volatile("st.relaxed.gpu.b32 [%0], %1;" :: "l"(p), "r"(v) : "memory");
}
__device__ __forceinline__ int atom_add_ar(int* p, int v) {
    int old;
    asm volatile("atom.acq_rel.gpu.add.s32 %0, [%1], %2;"
                 : "=r"(old) : "l"(p), "r"(v) : "memory");
    return old;
}

// single-level barrier: nb arrivals on group grp (LSTM grp 0..15; pairs grp 64+b)
__device__ __forceinline__ void group_barrier(int grp, int nb) {
    __syncthreads();
    if (threadIdx.x == 0) {
        int* cnt = g_bcnt + grp * 32;
        int* gen = g_bgen + grp * 32;
        int g0 = ld_acq(gen);
        if (atom_add_ar(cnt, 1) == nb - 1) {
            st_rlx(cnt, 0);
            st_rel(gen, g0 + 1);
        } else {
            while (ld_acq(gen) == g0) { }
        }
    }
    __syncthreads();
}

// two-level barrier for the 128-block decoder: 8 leaves x 16 + top of 8
#define DECB 1280
__device__ __forceinline__ void dec_barrier(int bid) {
    __syncthreads();
    if (threadIdx.x == 0) {
        int leaf = bid >> 4;
        int* lc  = g_bcnt + DECB + leaf * 32;
        int* tc  = g_bcnt + DECB + 8 * 32;
        int* gen = g_bgen + DECB;
        int g0 = ld_acq(gen);
        if (atom_add_ar(lc, 1) == 15) {
            if (atom_add_ar(tc, 1) == 7) {
#pragma unroll
                for (int l = 0; l < 8; l++) st_rlx(g_bcnt + DECB + l * 32, 0);
                st_rlx(tc, 0);
                st_rel(gen, g0 + 1);
            } else {
                while (ld_acq(gen) == g0) { }
            }
        } else {
            while (ld_acq(gen) == g0) { }
        }
    }
    __syncthreads();
}

// ---------------- warp-level fp16 MMA + ldmatrix + cp.async (sm_103-legal) ----------------
__device__ __forceinline__ void mma16816(float* c, const uint32_t* a, const uint32_t* b) {
    asm volatile(
        "mma.sync.aligned.m16n8k16.row.col.f32.f16.f16.f32 "
        "{%0,%1,%2,%3}, {%4,%5,%6,%7}, {%8,%9}, {%0,%1,%2,%3};"
        : "+f"(c[0]), "+f"(c[1]), "+f"(c[2]), "+f"(c[3])
        : "r"(a[0]), "r"(a[1]), "r"(a[2]), "r"(a[3]), "r"(b[0]), "r"(b[1]));
}
__device__ __forceinline__ void ldsm4(uint32_t* r, uint32_t a) {
    asm volatile("ldmatrix.sync.aligned.m8n8.x4.shared.b16 {%0,%1,%2,%3}, [%4];"
                 : "=r"(r[0]), "=r"(r[1]), "=r"(r[2]), "=r"(r[3]) : "r"(a));
}
__device__ __forceinline__ void cp16(uint32_t s, const void* g) {
    asm volatile("cp.async.cg.shared.global [%0], [%1], 16;" :: "r"(s), "l"(g));
}
__device__ __forceinline__ void cp_commit() {
    asm volatile("cp.async.commit_group;" ::: "memory");
}
template <int N>
__device__ __forceinline__ void cp_waitg() {
    asm volatile("cp.async.wait_group %0;" :: "n"(N) : "memory");
}

#define LDSW 72                       // smem row stride (64 data + 8 pad) in fp16
#define TILE_E (128 * LDSW)           // elems per tile buffer
#define STAGE_B (3 * TILE_E * 2)      // bytes per stage (A, Bhi, Blo)
#define TCSM (2 * STAGE_B)            // 110592 bytes, 2 stages

// ---------------- fp16 2-term split tensor-core GEMM, double-buffered ----------------
// C = A[M,K] @ (Bhi+Blo)[N,K]^T + bias.  mode 0: fp32 C. mode 1: fp32 scatter.
// mode 2: fp16 C (half* reinterpreted).
__global__ __launch_bounds__(256, 2) void gemm_tc(
    const __half* __restrict__ A,
    const __half* __restrict__ Bhi, const __half* __restrict__ Blo,
    const float* __restrict__ bias, float* __restrict__ C,
    int Mreal, int Nreal, int K, int mode)
{
    extern __shared__ __half sm[];
    uint32_t s0 = (uint32_t)__cvta_generic_to_shared(sm);

    int tid = threadIdx.x;
    int warp = tid >> 5, lane = tid & 31;
    int m0 = blockIdx.x * 128, n0 = blockIdx.y * 128;
    int mw = (warp >> 1) * 32, nw = (warp & 1) * 64;

    float acc[2][8][4];
#pragma unroll
    for (int i = 0; i < 2; i++)
#pragma unroll
        for (int j = 0; j < 8; j++)
#pragma unroll
            for (int q = 0; q < 4; q++) acc[i][j][q] = 0.f;

    int ar = lane >> 2;
    int acq = (lane & 3) * 2;

    uint32_t aoffB = (uint32_t)(((mw + (lane & 15)) * LDSW + (lane >> 4) * 8) * 2);
    int bq = lane >> 3, br = lane & 7;
    uint32_t boffB[4];
#pragma unroll
    for (int p = 0; p < 4; p++)
        boffB[p] = (uint32_t)(((nw + (2 * p + (bq >> 1)) * 8 + br) * LDSW + (bq & 1) * 8) * 2);
    const uint32_t MT_OFF = 16 * LDSW * 2;

    int srow = tid >> 3, sc8 = (tid & 7) * 8;
    int nc = K >> 6;

    auto load_chunk = [&](int c, int stg) {
        uint32_t base = s0 + (uint32_t)stg * STAGE_B;
#pragma unroll
        for (int i = 0; i < 4; i++) {
            int row = srow + i * 32;
            uint32_t so2 = (uint32_t)((row * LDSW + sc8) * 2);
            size_t ga = (size_t)(m0 + row) * K + c * 64 + sc8;
            size_t gb = (size_t)(n0 + row) * K + c * 64 + sc8;
            cp16(base + so2, A + ga);
            cp16(base + TILE_E * 2 + so2, Bhi + gb);
            cp16(base + 2 * TILE_E * 2 + so2, Blo + gb);
        }
        cp_commit();
    };

    load_chunk(0, 0);
    for (int c = 0; c < nc; c++) {
        int stg = c & 1;
        if (c + 1 < nc) {
            load_chunk(c + 1, stg ^ 1);
            cp_waitg<1>();
        } else {
            cp_waitg<0>();
        }
        __syncthreads();
        uint32_t sA32 = s0 + (uint32_t)stg * STAGE_B;
        uint32_t sBh32 = sA32 + TILE_E * 2;
        uint32_t sBl32 = sA32 + 2 * TILE_E * 2;
#pragma unroll
        for (int k16 = 0; k16 < 4; k16++) {
            uint32_t kby = (uint32_t)k16 * 32;
            uint32_t ah[2][4], bf[4][4];
            ldsm4(ah[0], sA32 + aoffB + kby);
            ldsm4(ah[1], sA32 + aoffB + MT_OFF + kby);
#pragma unroll
            for (int p = 0; p < 4; p++) ldsm4(bf[p], sBh32 + boffB[p] + kby);
#pragma unroll
            for (int mt = 0; mt < 2; mt++)
#pragma unroll
                for (int p = 0; p < 4; p++) {
                    mma16816(acc[mt][2 * p],     ah[mt], &bf[p][0]);   // A*Bhi
                    mma16816(acc[mt][2 * p + 1], ah[mt], &bf[p][2]);
                }
#pragma unroll
            for (int p = 0; p < 4; p++) ldsm4(bf[p], sBl32 + boffB[p] + kby);
#pragma unroll
            for (int mt = 0; mt < 2; mt++)
#pragma unroll
                for (int p = 0; p < 4; p++) {
                    mma16816(acc[mt][2 * p],     ah[mt], &bf[p][0]);   // A*Blo
                    mma16816(acc[mt][2 * p + 1], ah[mt], &bf[p][2]);
                }
        }
        __syncthreads();
    }

#pragma unroll
    for (int mt = 0; mt < 2; mt++) {
#pragma unroll
        for (int half = 0; half < 2; half++) {
            int m = m0 + mw + mt * 16 + ar + half * 8;
            if (m >= Mreal) continue;
#pragma unroll
            for (int nt = 0; nt < 8; nt++) {
                int col = n0 + nw + nt * 8 + acq;
                float v0 = acc[mt][nt][half * 2 + 0] + (bias ? bias[col] : 0.f);
                float v1 = acc[mt][nt][half * 2 + 1]
                         + ((bias && col + 1 < Nreal) ? bias[col + 1] : 0.f);
                if (mode == 2) {
                    __half* crow = ((__half*)C) + (size_t)m * Nreal;
                    if (col < Nreal)     crow[col]     = __float2half(v0);
                    if (col + 1 < Nreal) crow[col + 1] = __float2half(v1);
                } else {
                    float* crow;
                    if (mode == 1) {
                        int b = m & 63, st = m >> 6;
                        crow = C + ((size_t)b * Tsz + st + 1) * (size_t)Nreal;
                    } else {
                        crow = C + (size_t)m * Nreal;
                    }
                    if (col < Nreal)     crow[col]     = v0;
                    if (col + 1 < Nreal) crow[col + 1] = v1;
                }
            }
        }
    }
}

// ---------------- fused embed gather + fp16 convert (layer-1 A) ----------------
__global__ void emb_half(const int* __restrict__ src, const float* __restrict__ emb,
                         __half* __restrict__ dst) {
    int row = blockIdx.x, t = threadIdx.x;
    dst[(size_t)row * Esz + t] = __float2half(emb[(size_t)src[row] * Esz + t]);
}

// ---------------- one fused prep kernel: transposes + bias + weight splits ----------------
__global__ void prep_fused(
    const float* __restrict__ Wa,
    const float* __restrict__ w1f, const float* __restrict__ w1b,
    const float* __restrict__ w2f, const float* __restrict__ w2b,
    const float* __restrict__ dW,
    const float* __restrict__ b1f, const float* __restrict__ b1b,
    const float* __restrict__ b2f, const float* __restrict__ b2b,
    const float* __restrict__ e1f, const float* __restrict__ e1b,
    const float* __restrict__ e2f, const float* __restrict__ e2b,
    const float* __restrict__ Wfc,
    __half* __restrict__ Wa1TH, float* __restrict__ WhhT4,
    float* __restrict__ dWT4, float* __restrict__ b1c, float* __restrict__ b2c,
    float* __restrict__ hcTail, __half* __restrict__ hcHTail,
    __half* __restrict__ B1hi, __half* __restrict__ B1lo,
    __half* __restrict__ B2hi, __half* __restrict__ B2lo,
    __half* __restrict__ BWahi, __half* __restrict__ BWalo,
    __half* __restrict__ Bfchi, __half* __restrict__ Bfclo)
{
    int i = blockIdx.x * 256 + threadIdx.x;
    if (i < 65536) {                         // Wa1T (fp16)
        int r = i & 255, k = i >> 8;
        Wa1TH[k * 256 + r] = __float2half(Wa[r * 768 + k]);
        return;
    }
    i -= 65536;
    if (i < 4 * 262144) {                    // 4x Whh tpose4
        int d = i >> 18, j = i & 262143;
        int r = j & 1023, k = j >> 10;
        const float* s = (d == 0) ? w1f : (d == 1) ? w1b : (d == 2) ? w2f : w2b;
        WhhT4[(size_t)d * 262144 + (size_t)(k >> 2) * 4096 + r * 4 + (k & 3)] = s[r * 256 + k];
        return;
    }
    i -= 4 * 262144;
    if (i < 655360) {                        // dWih tpose4
        int r = i & 1023, k = i >> 10;
        dWT4[(size_t)(k >> 2) * 4096 + r * 4 + (k & 3)] = dW[r * 640 + k];
        return;
    }
    i -= 655360;
    if (i < 1024) { b1c[i] = b1f[i]; b1c[1024 + i] = b1b[i]; return; }
    i -= 1024;
    if (i < 1024) { b2c[i] = b2f[i]; b2c[1024 + i] = b2b[i]; return; }
    i -= 1024;
    if (i < 49152) { hcTail[i] = 0.f; return; }
    i -= 49152;
    if (i < 49152) { hcHTail[i] = __float2half(0.f); return; }
    i -= 49152;
    // ---- weight fp16 hi/lo splits ----
    float x; size_t di; __half* hi; __half* lo;
    if (i < 131072) {
        x = e1f[i]; di = i; hi = B1hi; lo = B1lo;
    } else if ((i -= 131072) < 131072) {
        x = e1b[i]; di = (size_t)131072 + i; hi = B1hi; lo = B1lo;
    } else if ((i -= 131072) < 524288) {
        x = e2f[i]; di = i; hi = B2hi; lo = B2lo;
    } else if ((i -= 524288) < 524288) {
        x = e2b[i]; di = (size_t)524288 + i; hi = B2hi; lo = B2lo;
    } else if ((i -= 524288) < 131072) {
        int r = i >> 9, c = i & 511;
        x = Wa[(size_t)r * 768 + 256 + c]; di = i; hi = BWahi; lo = BWalo;
    } else if ((i -= 131072) < VPAD * 768) {
        int r = i / 768, c = i - r * 768;
        x = (r < Vsz) ? Wfc[(size_t)r * 768 + c] : 0.f;
        di = i; hi = Bfchi; lo = Bfclo;
    } else return;
    __half h = __float2half(x);
    hi[di] = h;
    lo[di] = __float2half(x - __half2float(h));
}

// ---------------- weight-stationary persistent LSTM layer (R14 proven config) ----------------
#define LSTM_DSM (131072 + 8192)
__global__ __launch_bounds__(256) void lstm_layer(
    const float* __restrict__ xW, const float* __restrict__ WhhT4,
    float* __restrict__ hbuf, float* __restrict__ out, __half* __restrict__ outh)
{
    extern __shared__ char dsm[];
    float4* ws  = (float4*)dsm;                  // [64 k4][128 gj]
    float4* hsm = (float4*)(dsm + 131072);       // [8 bi][64 k4]
    __shared__ float part[4][32][8];

    int bid = blockIdx.x;
    int jc = bid & 7, bg = (bid >> 3) & 7, d = bid >> 6;
    int grp = d * 8 + bg;
    int tid = threadIdx.x;
    float* h0 = hbuf;
    float* h1 = hbuf + 2 * Bsz * Hsz;

    const float4* W4 = (const float4*)(WhhT4 + (size_t)d * 262144);
    for (int idx = tid; idx < 64 * 128; idx += 256) {
        int k4 = idx >> 7, gjl = idx & 127;
        int g = gjl >> 5, j = gjl & 31;
        ws[idx] = W4[(size_t)k4 * 1024 + g * 256 + jc * 32 + j];
    }
    for (int idx = tid; idx < 2048; idx += 256) {
        int bi = idx >> 8, k = idx & 255;
        h0[(d * 64 + bg * 8 + bi) * 256 + k] = 0.f;
    }
    int j2 = tid >> 3, bl = tid & 7;
    int jg = jc * 32 + j2;
    int b  = bg * 8 + bl;
    float creg = 0.f;
    int gj = tid >> 1, pr = tid & 1;

    // prefetch step-0 gate inputs
    int s0i = (d == 0) ? 0 : (Ssz - 1);
    const float* xr = xW + (size_t)(b * Ssz + s0i) * 2048 + d * 1024;
    float xg0 = xr[jg], xg1 = xr[256 + jg], xg2 = xr[512 + jg], xg3 = xr[768 + jg];
    group_barrier(grp, 8);

    for (int t = 0; t < Ssz; t++) {
        const float* hprev = (t & 1) ? h1 : h0;
        float* hnext = (t & 1) ? h0 : h1;
        int s = (d == 0) ? t : (Ssz - 1 - t);
        for (int idx = tid; idx < 512; idx += 256) {
            int bi = idx >> 6, k4 = idx & 63;
            hsm[idx] = __ldcg((const float4*)(hprev +
                           (size_t)(d * 64 + bg * 8 + bi) * 256) + k4);
        }
        __syncthreads();
        float a0 = 0.f, a1 = 0.f, a2 = 0.f, a3 = 0.f;
        const float4* hb = hsm + pr * 4 * 64;
#pragma unroll 4
        for (int k4 = 0; k4 < 64; k4++) {
            float4 w = ws[k4 * 128 + gj];
            float4 x0 = hb[k4], x1 = hb[64 + k4], x2 = hb[128 + k4], x3 = hb[192 + k4];
            a0 += w.x * x0.x + w.y * x0.y + w.z * x0.z + w.w * x0.w;
            a1 += w.x * x1.x + w.y * x1.y + w.z * x1.z + w.w * x1.w;
            a2 += w.x * x2.x + w.y * x2.y + w.z * x2.z + w.w * x2.w;
            a3 += w.x * x3.x + w.y * x3.y + w.z * x3.z + w.w * x3.w;
        }
        {
            int gg = gj >> 5, jj = gj & 31, bb = pr * 4;
            part[gg][jj][bb + 0] = a0;
            part[gg][jj][bb + 1] = a1;
            part[gg][jj][bb + 2] = a2;
            part[gg][jj][bb + 3] = a3;
        }
        __syncthreads();
        {
            float gi = part[0][j2][bl] + xg0;
            float gf = part[1][j2][bl] + xg1;
            float g_ = part[2][j2][bl] + xg2;
            float go = part[3][j2][bl] + xg3;
            creg = sigf(gf) * creg + sigf(gi) * tanf_(g_);
            float h = sigf(go) * tanf_(creg);
            hnext[(d * 64 + b) * 256 + jg] = h;
            size_t oidx = (size_t)(b * Ssz + s) * 512 + d * 256 + jg;
            if (out) out[oidx] = h;
            outh[oidx] = __float2half(h);
        }
        // prefetch next step's gate inputs before the barrier
        if (t + 1 < Ssz) {
            int sn = (d == 0) ? (t + 1) : (Ssz - 2 - t);
            const float* xr2 = xW + (size_t)(b * Ssz + sn) * 2048 + d * 1024;
            xg0 = xr2[jg]; xg1 = xr2[256 + jg]; xg2 = xr2[512 + jg]; xg3 = xr2[768 + jg];
        }
        group_barrier(grp, 8);
    }
}

// ---------------- persistent decoder: pair-split phase A, fp16 enc context ----------------
#define DEC_DSM (163840 + 20480)
__global__ __launch_bounds__(256) void decoder_all(
    const int* __restrict__ trg, const int* __restrict__ tfmask,
    const float* __restrict__ enc, const __half* __restrict__ encH,
    const __half* __restrict__ encWaH,
    const __half* __restrict__ Wa1TH, const float* __restrict__ ba,
    const float* __restrict__ vvec, const float* __restrict__ dWT4,
    const float* __restrict__ db, const float* __restrict__ demb,
    const float* __restrict__ Wfc, const float* __restrict__ bfc,
    float* __restrict__ xin, float* __restrict__ hid,
    float* __restrict__ hc, __half* __restrict__ hcH,
    float* __restrict__ scg, float* __restrict__ ctxp)
{
    extern __shared__ char dsm[];
    float4* dws = (float4*)dsm;                   // [160 k4][64 gj]
    float4* xs4 = (float4*)(dsm + 163840);        // [8 b][160 k4]
    __shared__ float hsm_[256], hwa_[256], vs_[256], sc_[128];
    __shared__ float redm_, reds_;
    __shared__ int tok_;
    __shared__ float partB[4][16][8];
    __shared__ float ax_[768];
    __shared__ float abv_[256];
    __shared__ int abi_[256];

    int bid = blockIdx.x, tid = threadIdx.x;
    int jcB = bid & 15, bgB = bid >> 4;
    int b = bid & 63, sh = bid >> 6;              // pair role: sh=0 primary, 1 helper

    vs_[tid] = vvec[tid];
    {
        const float4* dW4 = (const float4*)dWT4;
        for (int i2 = tid; i2 < 160 * 64; i2 += 256) {
            int k4 = i2 >> 6, gj2 = i2 & 63;
            int g = gj2 >> 4, jj = gj2 & 15;
            dws[i2] = dW4[(size_t)k4 * 1024 + g * 256 + jcB * 16 + jj];
        }
    }
    dec_barrier(bid);

    for (int st = 0; st < Tsz - 1; st++) {
        // ===== phase A: pair (b, b+64), s-range split =====
        if (st == 0) hsm_[tid] = enc[((size_t)b * Ssz + (Ssz - 1)) * 512 + tid];
        else         hsm_[tid] = __ldcg(&hid[b * 256 + tid]);

        if (sh == 0) {
            if (st == 0) {
                if (tid == 0) tok_ = trg[b * Tsz];
            } else if (tfmask[st] != 0) {
                if (tid == 0) tok_ = trg[b * Tsz + st];
            } else {
                const float* hcp = hc + ((size_t)(st - 1) * Bsz + b) * 768;
                for (int i = tid; i < 768; i += 256) ax_[i] = __ldcg(&hcp[i]);
                __syncthreads();
                float best = -1e30f; int bix = 0;
                for (int v0 = tid; v0 < Vsz; v0 += 256) {
                    float s = bfc[v0];
                    const float* wr = Wfc + (size_t)v0 * 768;
                    for (int k = 0; k < 768; k++) s += ax_[k] * wr[k];
                    if (s > best) { best = s; bix = v0; }
                }
                abv_[tid] = best; abi_[tid] = bix;
                __syncthreads();
                for (int off = 128; off; off >>= 1) {
                    if (tid < off) {
                        if (abv_[tid + off] > abv_[tid] ||
                            (abv_[tid + off] == abv_[tid] && abi_[tid + off] < abi_[tid])) {
                            abv_[tid] = abv_[tid + off];
                            abi_[tid] = abi_[tid + off];
                        }
                    }
                    __syncthreads();
                }
                if (tid == 0) tok_ = abi_[0];
            }
        }
        __syncthreads();
        if (sh == 0 && tid < 128) xin[b * 640 + tid] = demb[(size_t)tok_ * 128 + tid];

        // hWa (both blocks, full, fp16 weights)
        {
            float acc = ba[tid];
#pragma unroll 16
            for (int k = 0; k < 256; k++)
                acc += hsm_[k] * __half2float(Wa1TH[k * 256 + tid]);
            hwa_[tid] = acc;
        }
        __syncthreads();

        // energies for own 64-s half -> global scores
        {
            int w = tid >> 5, l = tid & 31;
#pragma unroll
            for (int i = 0; i < 8; i++) {
                int s = sh * 64 + w * 8 + i;
                const __half* ep = encWaH + ((size_t)b * Ssz + s) * 256;
                float a2 = 0.f;
#pragma unroll
                for (int q = 0; q < 8; q++) {
                    int h = l + q * 32;
                    a2 += tanf_(hwa_[h] + __half2float(ep[h])) * vs_[h];
                }
#pragma unroll
                for (int o = 16; o; o >>= 1) a2 += __shfl_xor_sync(0xFFFFFFFFu, a2, o);
                if (l == 0) scg[b * 128 + s] = a2;
            }
        }
        group_barrier(64 + b, 2);                 // pair exchange: scores

        if (tid < 128) sc_[tid] = __ldcg(&scg[b * 128 + tid]);
        __syncthreads();
        if (tid < 32) {
            float m = fmaxf(fmaxf(sc_[tid], sc_[tid + 32]),
                            fmaxf(sc_[tid + 64], sc_[tid + 96]));
#pragma unroll
            for (int o = 16; o; o >>= 1) m = fmaxf(m, __shfl_xor_sync(0xFFFFFFFFu, m, o));
            if (tid == 0) redm_ = m;
        }
        __syncthreads();
        float mx = redm_;
        if (tid < 128) sc_[tid] = __expf(sc_[tid] - mx);
        __syncthreads();
        if (tid < 32) {
            float s_ = sc_[tid] + sc_[tid + 32] + sc_[tid + 64] + sc_[tid + 96];
#pragma unroll
            for (int o = 16; o; o >>= 1) s_ += __shfl_xor_sync(0xFFFFFFFFu, s_, o);
            if (tid == 0) reds_ = __fdividef(1.f, s_);
        }
        __syncthreads();
        {
            float inv = reds_;
            float c0 = 0.f, c1 = 0.f;
            const __half* eb = encH + (size_t)b * Ssz * 512 + (size_t)sh * 64 * 512;
#pragma unroll 8
            for (int s = 0; s < 64; s++) {
                float a = sc_[sh * 64 + s] * inv;
                c0 += a * __half2float(eb[s * 512 + tid]);
                c1 += a * __half2float(eb[s * 512 + 256 + tid]);
            }
            if (sh == 1) {
                ctxp[b * 512 + tid]       = c0;
                ctxp[b * 512 + 256 + tid] = c1;
            }
            group_barrier(64 + b, 2);             // pair exchange: partial context
            if (sh == 0) {
                c0 += __ldcg(&ctxp[b * 512 + tid]);
                c1 += __ldcg(&ctxp[b * 512 + 256 + tid]);
                xin[b * 640 + 128 + tid] = c0;
                xin[b * 640 + 384 + tid] = c1;
                size_t hcb = ((size_t)st * Bsz + b) * 768;
                hc[hcb + 256 + tid] = c0;
                hc[hcb + 512 + tid] = c1;
                hcH[hcb + 256 + tid] = __float2half(c0);
                hcH[hcb + 512 + tid] = __float2half(c1);
            }
        }
        dec_barrier(bid);

        // ===== phase B: gates, all 128 blocks =====
        {
            for (int i2 = tid; i2 < 8 * 160; i2 += 256) {
                int bi = i2 / 160, k4 = i2 - bi * 160;
                xs4[i2] = __ldcg((const float4*)(xin +
                               (size_t)(bgB * 8 + bi) * 640) + k4);
            }
            __syncthreads();
            int g = tid >> 6, jj = (tid >> 2) & 15, bq = tid & 3;
            float s0 = 0.f, s1 = 0.f;
            const float4* xa = xs4 + (bq * 2) * 160;
            const float4* xb = xs4 + (bq * 2 + 1) * 160;
            const float4* wp = dws + (g * 16 + jj);
#pragma unroll 4
            for (int k4 = 0; k4 < 160; k4++) {
                float4 w = wp[k4 * 64];
                float4 xA = xa[k4], xB = xb[k4];
                s0 += w.x * xA.x + w.y * xA.y + w.z * xA.z + w.w * xA.w;
                s1 += w.x * xB.x + w.y * xB.y + w.z * xB.z + w.w * xB.w;
            }
            partB[g][jj][bq * 2]     = s0;
            partB[g][jj][bq * 2 + 1] = s1;
            __syncthreads();
            if (tid < 128) {
                int jjf = tid >> 3, blf = tid & 7;
                int jgf = jcB * 16 + jjf, bbf = bgB * 8 + blf;
                float gi = partB[0][jjf][blf] + db[jgf];
                float g2 = partB[2][jjf][blf] + db[512 + jgf];
                float go = partB[3][jjf][blf] + db[768 + jgf];
                float cc = sigf(gi) * tanf_(g2);
                float hh = sigf(go) * tanf_(cc);
                hid[bbf * 256 + jgf] = hh;
                size_t hci = ((size_t)st * Bsz + bbf) * 768 + jgf;
                hc[hci] = hh;
                hcH[hci] = __float2half(hh);
            }
        }
        dec_barrier(bid);
    }
}

__global__ void zero_t0(float* __restrict__ out) {
    int b = blockIdx.x;
    int v = blockIdx.y * 256 + threadIdx.x;
    if (v < Vsz) out[(size_t)b * Tsz * Vsz + v] = 0.f;
}

// ---------------- host launch ----------------
static float* symaddr(const void* sym) {
    void* p = nullptr;
    cudaGetSymbolAddress(&p, sym);
    return (float*)p;
}
static __half* symaddrh(const void* sym) {
    void* p = nullptr;
    cudaGetSymbolAddress(&p, sym);
    return (__half*)p;
}

extern "C" void kernel_launch(void* const* d_in, const int* in_sizes, int n_in,
                              void* d_out, int out_size) {
    const int*   src     = (const int*)d_in[0];
    const int*   trg     = (const int*)d_in[1];
    const int*   tfmask  = (const int*)d_in[2];
    const float* enc_emb = (const float*)d_in[3];
    const float* e1f_Wih = (const float*)d_in[4];
    const float* e1f_Whh = (const float*)d_in[5];
    const float* e1f_b   = (const float*)d_in[6];
    const float* e1b_Wih = (const float*)d_in[7];
    const float* e1b_Whh = (const float*)d_in[8];
    const float* e1b_b   = (const float*)d_in[9];
    const float* e2f_Wih = (const float*)d_in[10];
    const float* e2f_Whh = (const float*)d_in[11];
    const float* e2f_b   = (const float*)d_in[12];
    const float* e2b_Wih = (const float*)d_in[13];
    const float* e2b_Whh = (const float*)d_in[14];
    const float* e2b_b   = (const float*)d_in[15];
    const float* dec_emb = (const float*)d_in[16];
    const float* Wa      = (const float*)d_in[17];
    const float* ba      = (const float*)d_in[18];
    const float* vvec    = (const float*)d_in[19];
    const float* dWih    = (const float*)d_in[20];
    const float* db      = (const float*)d_in[21];
    const float* Wfc     = (const float*)d_in[22];
    const float* bfc     = (const float*)d_in[23];
    float* out = (float*)d_out;

    float* p_xW    = symaddr(g_xW);
    float* p_enc   = symaddr(g_enc);
    float* p_b1c   = symaddr(g_b1c);
    float* p_b2c   = symaddr(g_b2c);
    float* p_WhhT4 = symaddr(g_WhhT4);
    float* p_dWT4  = symaddr(g_dWT4);
    float* p_h     = symaddr(g_h);
    float* p_hid   = symaddr(g_hid);
    float* p_xin   = symaddr(g_xin);
    float* p_hc    = symaddr(g_hc);
    float* p_scg   = symaddr(g_scg);
    float* p_ctxp  = symaddr(g_ctxp);

    __half* p_Ah     = symaddrh(g_Ah);
    __half* p_hcH    = symaddrh(g_hcH);
    __half* p_encWaH = symaddrh(g_encWaH);
    __half* p_Wa1TH  = symaddrh(g_Wa1TH);
    __half* p_B1hi = symaddrh(g_B1hi), * p_B1lo = symaddrh(g_B1lo);
    __half* p_B2hi = symaddrh(g_B2hi), * p_B2lo = symaddrh(g_B2lo);
    __half* p_BWahi = symaddrh(g_BWahi), * p_BWalo = symaddrh(g_BWalo);
    __half* p_Bfchi = symaddrh(g_Bfchi), * p_Bfclo = symaddrh(g_Bfclo);

    cudaFuncSetAttribute(gemm_tc, cudaFuncAttributeMaxDynamicSharedMemorySize, TCSM);
    cudaFuncSetAttribute(lstm_layer, cudaFuncAttributeMaxDynamicSharedMemorySize, LSTM_DSM);
    cudaFuncSetAttribute(decoder_all, cudaFuncAttributeMaxDynamicSharedMemorySize, DEC_DSM);

    auto nb = [](int n) { return (n + 255) / 256; };

    // [1] fused prep
    const int PREP_N = 65536 + 4 * 262144 + 655360 + 1024 + 1024 + 49152 + 49152
                     + 131072 + 131072 + 524288 + 524288 + 131072 + VPAD * 768;
    prep_fused<<<nb(PREP_N), 256>>>(
        Wa, e1f_Whh, e1b_Whh, e2f_Whh, e2b_Whh, dWih,
        e1f_b, e1b_b, e2f_b, e2b_b,
        e1f_Wih, e1b_Wih, e2f_Wih, e2b_Wih, Wfc,
        p_Wa1TH, p_WhhT4, p_dWT4, p_b1c, p_b2c,
        p_hc + (size_t)4032 * 768, p_hcH + (size_t)4032 * 768,
        p_B1hi, p_B1lo, p_B2hi, p_B2lo, p_BWahi, p_BWalo, p_Bfchi, p_Bfclo);
    // [2] embed + fp16 convert fused
    emb_half<<<Bsz * Ssz, Esz>>>(src, enc_emb, p_Ah);
    // [3] layer-1 GEMM
    gemm_tc<<<dim3(64, 16), 256, TCSM>>>(p_Ah, p_B1hi, p_B1lo,
                                         p_b1c, p_xW, 8192, 2048, 128, 0);
    // [4] layer-1 recurrence (R14 config: 128 blocks)
    lstm_layer<<<128, 256, LSTM_DSM>>>(p_xW, p_WhhT4, p_h, nullptr, p_Ah);
    // [5] layer-2 GEMM
    gemm_tc<<<dim3(64, 16), 256, TCSM>>>(p_Ah, p_B2hi, p_B2lo,
                                         p_b2c, p_xW, 8192, 2048, 512, 0);
    // [6] layer-2 recurrence (fp32 enc + fp16 into p_Ah, reused by decoder)
    lstm_layer<<<128, 256, LSTM_DSM>>>(p_xW, p_WhhT4 + 2 * 262144, p_h, p_enc, p_Ah);
    // [7] attention precompute GEMM -> fp16 encWa
    gemm_tc<<<dim3(64, 2), 256, TCSM>>>(p_Ah, p_BWahi, p_BWalo,
                                        nullptr, (float*)p_encWaH, 8192, 256, 512, 2);
    // [8] persistent decoder (pair-split phase A; fp16 enc for context)
    decoder_all<<<128, 256, DEC_DSM>>>(trg, tfmask, p_enc, p_Ah, p_encWaH, p_Wa1TH,
                                       ba, vvec, p_dWT4, db, dec_emb, Wfc, bfc,
                                       p_xin, p_hid, p_hc, p_hcH, p_scg, p_ctxp);
    // [9] final projection (scatter into out)
    gemm_tc<<<dim3(32, 79), 256, TCSM>>>(p_hcH, p_Bfchi, p_Bfclo,
                                         bfc, out, 4032, Vsz, 768, 1);
    // [10] zero t=0 outputs
    zero_t0<<<dim3(Bsz, (Vsz + 255) / 256), 256>>>(out);
}

// round 17
// speedup vs baseline: 1.6844x; 1.0665x over previous
#include <cuda_runtime.h>
#include <cuda_fp16.h>
#include <stdint.h>
#include <stddef.h>

#define Bsz 64
#define Ssz 128
#define Tsz 64
#define Vsz 10000
#define Esz 128
#define Hsz 256
#define VPAD 10112            // V padded to multiple of 128

// ---------------- device scratch (no dynamic allocation allowed) ----------------
__device__ float g_xW[Bsz * Ssz * 2048];
__device__ float g_enc[Bsz * Ssz * 2 * Hsz];
__device__ float g_b1c[2048];
__device__ float g_b2c[2048];
__device__ float g_WhhT4[4 * 256 * 1024];
__device__ float g_dWT4[640 * 1024];
__device__ float g_h[2][2 * Bsz * Hsz];             // double-buffered h state
__device__ float g_hid[Bsz * Hsz];
__device__ float g_xin[Bsz * 640];
__device__ float g_hc[4096 * 768];                  // fp32 [h,ctx] (argmax fallback)
__device__ float g_scg[Bsz * 128];                  // attention scores exchange
__device__ float g_ctxp[Bsz * 512];                 // helper partial context

// barrier state (zero-initialized; generation-based, self-resetting, replay-safe)
__device__ int g_bcnt[8192];
__device__ int g_bgen[8192];

// fp16 buffers
__device__ __half g_Ah[8192 * 512];
__device__ __half g_hcH[4096 * 768];                // fp16 [h,ctx]; tail zeroed
__device__ __half g_encWaH[8192 * 256];             // fp16 enc@Wa2.T
__device__ __half g_Wa1TH[256 * 256];               // fp16 Wa1 transposed
__device__ __half g_B1hi[2048 * 128], g_B1lo[2048 * 128];
__device__ __half g_B2hi[2048 * 512], g_B2lo[2048 * 512];
__device__ __half g_BWahi[256 * 512], g_BWalo[256 * 512];
__device__ __half g_Bfchi[VPAD * 768], g_Bfclo[VPAD * 768];

// ---------------- fast math helpers ----------------
__device__ __forceinline__ float sigf(float x) {
    return __fdividef(1.f, 1.f + __expf(-x));
}
__device__ __forceinline__ float tanf_(float x) {
    x = fminf(fmaxf(x, -15.f), 15.f);
    float e = __expf(2.f * x);
    return __fdividef(e - 1.f, e + 1.f);
}

// ---------------- release/acquire barrier primitives (no full fences) ----------------
__device__ __forceinline__ int ld_acq(const int* p) {
    int v;
    asm volatile("ld.acquire.gpu.b32 %0, [%1];" : "=r"(v) : "l"(p) : "memory");
    return v;
}
__device__ __forceinline__ void st_rel(int* p, int v) {
    asm volatile("st.release.gpu.b32 [%0], %1;" :: "l"(p), "r"(v) : "memory");
}
__device__ __forceinline__ void st_rlx(int* p, int v) {
    asm volatile("st.relaxed.gpu.b32 [%0], %1;" :: "l"(p), "r"(v) : "memory");
}
__device__ __forceinline__ int atom_add_ar(int* p, int v) {
    int old;
    asm volatile("atom.acq_rel.gpu.add.s32 %0, [%1], %2;"
                 : "=r"(old) : "l"(p), "r"(v) : "memory");
    return old;
}

// single-level barrier: nb arrivals on group grp (LSTM grp 0..15; pairs grp 64+b)
__device__ __forceinline__ void group_barrier(int grp, int nb) {
    __syncthreads();
    if (threadIdx.x == 0) {
        int* cnt = g_bcnt + grp * 32;
        int* gen = g_bgen + grp * 32;
        int g0 = ld_acq(gen);
        if (atom_add_ar(cnt, 1) == nb - 1) {
            st_rlx(cnt, 0);
            st_rel(gen, g0 + 1);
        } else {
            while (ld_acq(gen) == g0) { }
        }
    }
    __syncthreads();
}

// two-level barrier for the 128-block decoder: 8 leaves x 16 + top of 8
#define DECB 1280
__device__ __forceinline__ void dec_barrier(int bid) {
    __syncthreads();
    if (threadIdx.x == 0) {
        int leaf = bid >> 4;
        int* lc  = g_bcnt + DECB + leaf * 32;
        int* tc  = g_bcnt + DECB + 8 * 32;
        int* gen = g_bgen + DECB;
        int g0 = ld_acq(gen);
        if (atom_add_ar(lc, 1) == 15) {
            if (atom_add_ar(tc, 1) == 7) {
#pragma unroll
                for (int l = 0; l < 8; l++) st_rlx(g_bcnt + DECB + l * 32, 0);
                st_rlx(tc, 0);
                st_rel(gen, g0 + 1);
            } else {
                while (ld_acq(gen) == g0) { }
            }
        } else {
            while (ld_acq(gen) == g0) { }
        }
    }
    __syncthreads();
}

// ---------------- warp-level fp16 MMA + ldmatrix + cp.async (sm_103-legal) ----------------
__device__ __forceinline__ void mma16816(float* c, const uint32_t* a, const uint32_t* b) {
    asm volatile(
        "mma.sync.aligned.m16n8k16.row.col.f32.f16.f16.f32 "
        "{%0,%1,%2,%3}, {%4,%5,%6,%7}, {%8,%9}, {%0,%1,%2,%3};"
        : "+f"(c[0]), "+f"(c[1]), "+f"(c[2]), "+f"(c[3])
        : "r"(a[0]), "r"(a[1]), "r"(a[2]), "r"(a[3]), "r"(b[0]), "r"(b[1]));
}
__device__ __forceinline__ void ldsm4(uint32_t* r, uint32_t a) {
    asm volatile("ldmatrix.sync.aligned.m8n8.x4.shared.b16 {%0,%1,%2,%3}, [%4];"
                 : "=r"(r[0]), "=r"(r[1]), "=r"(r[2]), "=r"(r[3]) : "r"(a));
}
__device__ __forceinline__ void cp16(uint32_t s, const void* g) {
    asm volatile("cp.async.cg.shared.global [%0], [%1], 16;" :: "r"(s), "l"(g));
}
__device__ __forceinline__ void cp_commit() {
    asm volatile("cp.async.commit_group;" ::: "memory");
}
template <int N>
__device__ __forceinline__ void cp_waitg() {
    asm volatile("cp.async.wait_group %0;" :: "n"(N) : "memory");
}

#define LDSW 72                       // smem row stride (64 data + 8 pad) in fp16
#define TILE_E (128 * LDSW)           // elems per tile buffer
#define STAGE_B (3 * TILE_E * 2)      // bytes per stage (A, Bhi, Blo)
#define TCSM (2 * STAGE_B)            // 110592 bytes, 2 stages

// ---------------- fp16 2-term split tensor-core GEMM, double-buffered ----------------
// C = A[M,K] @ (Bhi+Blo)[N,K]^T + bias.  mode 0: fp32 C. mode 1: fp32 scatter.
// mode 2: fp16 C (half* reinterpreted).
__global__ __launch_bounds__(256, 2) void gemm_tc(
    const __half* __restrict__ A,
    const __half* __restrict__ Bhi, const __half* __restrict__ Blo,
    const float* __restrict__ bias, float* __restrict__ C,
    int Mreal, int Nreal, int K, int mode)
{
    extern __shared__ __half sm[];
    uint32_t s0 = (uint32_t)__cvta_generic_to_shared(sm);

    int tid = threadIdx.x;
    int warp = tid >> 5, lane = tid & 31;
    int m0 = blockIdx.x * 128, n0 = blockIdx.y * 128;
    int mw = (warp >> 1) * 32, nw = (warp & 1) * 64;

    float acc[2][8][4];
#pragma unroll
    for (int i = 0; i < 2; i++)
#pragma unroll
        for (int j = 0; j < 8; j++)
#pragma unroll
            for (int q = 0; q < 4; q++) acc[i][j][q] = 0.f;

    int ar = lane >> 2;
    int acq = (lane & 3) * 2;

    uint32_t aoffB = (uint32_t)(((mw + (lane & 15)) * LDSW + (lane >> 4) * 8) * 2);
    int bq = lane >> 3, br = lane & 7;
    uint32_t boffB[4];
#pragma unroll
    for (int p = 0; p < 4; p++)
        boffB[p] = (uint32_t)(((nw + (2 * p + (bq >> 1)) * 8 + br) * LDSW + (bq & 1) * 8) * 2);
    const uint32_t MT_OFF = 16 * LDSW * 2;

    int srow = tid >> 3, sc8 = (tid & 7) * 8;
    int nc = K >> 6;

    auto load_chunk = [&](int c, int stg) {
        uint32_t base = s0 + (uint32_t)stg * STAGE_B;
#pragma unroll
        for (int i = 0; i < 4; i++) {
            int row = srow + i * 32;
            uint32_t so2 = (uint32_t)((row * LDSW + sc8) * 2);
            size_t ga = (size_t)(m0 + row) * K + c * 64 + sc8;
            size_t gb = (size_t)(n0 + row) * K + c * 64 + sc8;
            cp16(base + so2, A + ga);
            cp16(base + TILE_E * 2 + so2, Bhi + gb);
            cp16(base + 2 * TILE_E * 2 + so2, Blo + gb);
        }
        cp_commit();
    };

    load_chunk(0, 0);
    for (int c = 0; c < nc; c++) {
        int stg = c & 1;
        if (c + 1 < nc) {
            load_chunk(c + 1, stg ^ 1);
            cp_waitg<1>();
        } else {
            cp_waitg<0>();
        }
        __syncthreads();
        uint32_t sA32 = s0 + (uint32_t)stg * STAGE_B;
        uint32_t sBh32 = sA32 + TILE_E * 2;
        uint32_t sBl32 = sA32 + 2 * TILE_E * 2;
#pragma unroll
        for (int k16 = 0; k16 < 4; k16++) {
            uint32_t kby = (uint32_t)k16 * 32;
            uint32_t ah[2][4], bf[4][4];
            ldsm4(ah[0], sA32 + aoffB + kby);
            ldsm4(ah[1], sA32 + aoffB + MT_OFF + kby);
#pragma unroll
            for (int p = 0; p < 4; p++) ldsm4(bf[p], sBh32 + boffB[p] + kby);
#pragma unroll
            for (int mt = 0; mt < 2; mt++)
#pragma unroll
                for (int p = 0; p < 4; p++) {
                    mma16816(acc[mt][2 * p],     ah[mt], &bf[p][0]);   // A*Bhi
                    mma16816(acc[mt][2 * p + 1], ah[mt], &bf[p][2]);
                }
#pragma unroll
            for (int p = 0; p < 4; p++) ldsm4(bf[p], sBl32 + boffB[p] + kby);
#pragma unroll
            for (int mt = 0; mt < 2; mt++)
#pragma unroll
                for (int p = 0; p < 4; p++) {
                    mma16816(acc[mt][2 * p],     ah[mt], &bf[p][0]);   // A*Blo
                    mma16816(acc[mt][2 * p + 1], ah[mt], &bf[p][2]);
                }
        }
        __syncthreads();
    }

#pragma unroll
    for (int mt = 0; mt < 2; mt++) {
#pragma unroll
        for (int half = 0; half < 2; half++) {
            int m = m0 + mw + mt * 16 + ar + half * 8;
            if (m >= Mreal) continue;
#pragma unroll
            for (int nt = 0; nt < 8; nt++) {
                int col = n0 + nw + nt * 8 + acq;
                float v0 = acc[mt][nt][half * 2 + 0] + (bias ? bias[col] : 0.f);
                float v1 = acc[mt][nt][half * 2 + 1]
                         + ((bias && col + 1 < Nreal) ? bias[col + 1] : 0.f);
                if (mode == 2) {
                    __half* crow = ((__half*)C) + (size_t)m * Nreal;
                    if (col < Nreal)     crow[col]     = __float2half(v0);
                    if (col + 1 < Nreal) crow[col + 1] = __float2half(v1);
                } else {
                    float* crow;
                    if (mode == 1) {
                        int b = m & 63, st = m >> 6;
                        crow = C + ((size_t)b * Tsz + st + 1) * (size_t)Nreal;
                    } else {
                        crow = C + (size_t)m * Nreal;
                    }
                    if (col < Nreal)     crow[col]     = v0;
                    if (col + 1 < Nreal) crow[col + 1] = v1;
                }
            }
        }
    }
}

// ---------------- fused embed gather + fp16 convert (layer-1 A) ----------------
__global__ void emb_half(const int* __restrict__ src, const float* __restrict__ emb,
                         __half* __restrict__ dst) {
    int row = blockIdx.x, t = threadIdx.x;
    dst[(size_t)row * Esz + t] = __float2half(emb[(size_t)src[row] * Esz + t]);
}

// ---------------- one fused prep kernel: transposes + bias + weight splits ----------------
__global__ void prep_fused(
    const float* __restrict__ Wa,
    const float* __restrict__ w1f, const float* __restrict__ w1b,
    const float* __restrict__ w2f, const float* __restrict__ w2b,
    const float* __restrict__ dW,
    const float* __restrict__ b1f, const float* __restrict__ b1b,
    const float* __restrict__ b2f, const float* __restrict__ b2b,
    const float* __restrict__ e1f, const float* __restrict__ e1b,
    const float* __restrict__ e2f, const float* __restrict__ e2b,
    const float* __restrict__ Wfc,
    __half* __restrict__ Wa1TH, float* __restrict__ WhhT4,
    float* __restrict__ dWT4, float* __restrict__ b1c, float* __restrict__ b2c,
    float* __restrict__ hcTail, __half* __restrict__ hcHTail,
    __half* __restrict__ B1hi, __half* __restrict__ B1lo,
    __half* __restrict__ B2hi, __half* __restrict__ B2lo,
    __half* __restrict__ BWahi, __half* __restrict__ BWalo,
    __half* __restrict__ Bfchi, __half* __restrict__ Bfclo)
{
    int i = blockIdx.x * 256 + threadIdx.x;
    if (i < 65536) {                         // Wa1T (fp16)
        int r = i & 255, k = i >> 8;
        Wa1TH[k * 256 + r] = __float2half(Wa[r * 768 + k]);
        return;
    }
    i -= 65536;
    if (i < 4 * 262144) {                    // 4x Whh tpose4
        int d = i >> 18, j = i & 262143;
        int r = j & 1023, k = j >> 10;
        const float* s = (d == 0) ? w1f : (d == 1) ? w1b : (d == 2) ? w2f : w2b;
        WhhT4[(size_t)d * 262144 + (size_t)(k >> 2) * 4096 + r * 4 + (k & 3)] = s[r * 256 + k];
        return;
    }
    i -= 4 * 262144;
    if (i < 655360) {                        // dWih tpose4
        int r = i & 1023, k = i >> 10;
        dWT4[(size_t)(k >> 2) * 4096 + r * 4 + (k & 3)] = dW[r * 640 + k];
        return;
    }
    i -= 655360;
    if (i < 1024) { b1c[i] = b1f[i]; b1c[1024 + i] = b1b[i]; return; }
    i -= 1024;
    if (i < 1024) { b2c[i] = b2f[i]; b2c[1024 + i] = b2b[i]; return; }
    i -= 1024;
    if (i < 49152) { hcTail[i] = 0.f; return; }
    i -= 49152;
    if (i < 49152) { hcHTail[i] = __float2half(0.f); return; }
    i -= 49152;
    // ---- weight fp16 hi/lo splits ----
    float x; size_t di; __half* hi; __half* lo;
    if (i < 131072) {
        x = e1f[i]; di = i; hi = B1hi; lo = B1lo;
    } else if ((i -= 131072) < 131072) {
        x = e1b[i]; di = (size_t)131072 + i; hi = B1hi; lo = B1lo;
    } else if ((i -= 131072) < 524288) {
        x = e2f[i]; di = i; hi = B2hi; lo = B2lo;
    } else if ((i -= 524288) < 524288) {
        x = e2b[i]; di = (size_t)524288 + i; hi = B2hi; lo = B2lo;
    } else if ((i -= 524288) < 131072) {
        int r = i >> 9, c = i & 511;
        x = Wa[(size_t)r * 768 + 256 + c]; di = i; hi = BWahi; lo = BWalo;
    } else if ((i -= 131072) < VPAD * 768) {
        int r = i / 768, c = i - r * 768;
        x = (r < Vsz) ? Wfc[(size_t)r * 768 + c] : 0.f;
        di = i; hi = Bfchi; lo = Bfclo;
    } else return;
    __half h = __float2half(x);
    hi[di] = h;
    lo[di] = __float2half(x - __half2float(h));
}

// ---------------- weight-stationary persistent LSTM layer ----------------
// New inner loop: 4col x 4batch outer product with 4-way split-K (2 B/FMA),
// padded smem (ws rows 130 float4, hsm rows 65 float4) for conflict reduction.
#define LSTM_DSM (64 * 130 * 16 + 8 * 65 * 16)     // 133120 + 8320 = 141440
__global__ __launch_bounds__(256) void lstm_layer(
    const float* __restrict__ xW, const float* __restrict__ WhhT4,
    float* __restrict__ hbuf, float* __restrict__ out, __half* __restrict__ outh)
{
    extern __shared__ char dsm[];
    float4* ws  = (float4*)dsm;                      // [64 k4][130 pad] cols 0..127
    float4* hsm = (float4*)(dsm + 64 * 130 * 16);    // [8 bi][65 pad]
    __shared__ float part[4][32][8];

    int bid = blockIdx.x;
    int jc = bid & 7, bg = (bid >> 3) & 7, d = bid >> 6;
    int grp = d * 8 + bg;
    int tid = threadIdx.x;
    float* h0 = hbuf;
    float* h1 = hbuf + 2 * Bsz * Hsz;

    const float4* W4 = (const float4*)(WhhT4 + (size_t)d * 262144);
    for (int idx = tid; idx < 64 * 128; idx += 256) {
        int k4 = idx >> 7, gjl = idx & 127;
        int g = gjl >> 5, j = gjl & 31;
        ws[k4 * 130 + gjl] = W4[(size_t)k4 * 1024 + g * 256 + jc * 32 + j];
    }
    for (int idx = tid; idx < 2048; idx += 256) {
        int bi = idx >> 8, k = idx & 255;
        h0[(d * 64 + bg * 8 + bi) * 256 + k] = 0.f;
    }
    int j2 = tid >> 3, bl = tid & 7;            // finalize map
    int jg = jc * 32 + j2;
    int b  = bg * 8 + bl;
    float creg = 0.f;
    // compute map: kg (split-K quarter), bgr (batch half), cg (col group)
    int kg  = tid & 3;
    int bgr = (tid >> 2) & 1;
    int cg  = tid >> 3;                          // 0..31; cols c*32+cg (c=0..3 = gate)

    // prefetch step-0 gate inputs
    int s0i = (d == 0) ? 0 : (Ssz - 1);
    const float* xr = xW + (size_t)(b * Ssz + s0i) * 2048 + d * 1024;
    float xg0 = xr[jg], xg1 = xr[256 + jg], xg2 = xr[512 + jg], xg3 = xr[768 + jg];
    group_barrier(grp, 8);

    for (int t = 0; t < Ssz; t++) {
        const float* hprev = (t & 1) ? h1 : h0;
        float* hnext = (t & 1) ? h0 : h1;
        int s = (d == 0) ? t : (Ssz - 1 - t);
        for (int idx = tid; idx < 512; idx += 256) {
            int bi = idx >> 6, k4 = idx & 63;
            hsm[bi * 65 + k4] = __ldcg((const float4*)(hprev +
                           (size_t)(d * 64 + bg * 8 + bi) * 256) + k4);
        }
        __syncthreads();
        float acc[4][4];
#pragma unroll
        for (int c = 0; c < 4; c++)
#pragma unroll
            for (int q = 0; q < 4; q++) acc[c][q] = 0.f;
        const float4* hbase = hsm + (bgr * 4) * 65;
#pragma unroll 4
        for (int i = 0; i < 16; i++) {
            int k4 = (i << 2) + kg;
            const float4* wp = ws + k4 * 130 + cg;
            float4 w0 = wp[0], w1 = wp[32], w2 = wp[64], w3 = wp[96];
            float4 hv0 = hbase[k4], hv1 = hbase[65 + k4];
            float4 hv2 = hbase[130 + k4], hv3 = hbase[195 + k4];
            acc[0][0] += w0.x*hv0.x + w0.y*hv0.y + w0.z*hv0.z + w0.w*hv0.w;
            acc[0][1] += w0.x*hv1.x + w0.y*hv1.y + w0.z*hv1.z + w0.w*hv1.w;
            acc[0][2] += w0.x*hv2.x + w0.y*hv2.y + w0.z*hv2.z + w0.w*hv2.w;
            acc[0][3] += w0.x*hv3.x + w0.y*hv3.y + w0.z*hv3.z + w0.w*hv3.w;
            acc[1][0] += w1.x*hv0.x + w1.y*hv0.y + w1.z*hv0.z + w1.w*hv0.w;
            acc[1][1] += w1.x*hv1.x + w1.y*hv1.y + w1.z*hv1.z + w1.w*hv1.w;
            acc[1][2] += w1.x*hv2.x + w1.y*hv2.y + w1.z*hv2.z + w1.w*hv2.w;
            acc[1][3] += w1.x*hv3.x + w1.y*hv3.y + w1.z*hv3.z + w1.w*hv3.w;
            acc[2][0] += w2.x*hv0.x + w2.y*hv0.y + w2.z*hv0.z + w2.w*hv0.w;
            acc[2][1] += w2.x*hv1.x + w2.y*hv1.y + w2.z*hv1.z + w2.w*hv1.w;
            acc[2][2] += w2.x*hv2.x + w2.y*hv2.y + w2.z*hv2.z + w2.w*hv2.w;
            acc[2][3] += w2.x*hv3.x + w2.y*hv3.y + w2.z*hv3.z + w2.w*hv3.w;
            acc[3][0] += w3.x*hv0.x + w3.y*hv0.y + w3.z*hv0.z + w3.w*hv0.w;
            acc[3][1] += w3.x*hv1.x + w3.y*hv1.y + w3.z*hv1.z + w3.w*hv1.w;
            acc[3][2] += w3.x*hv2.x + w3.y*hv2.y + w3.z*hv2.z + w3.w*hv2.w;
            acc[3][3] += w3.x*hv3.x + w3.y*hv3.y + w3.z*hv3.z + w3.w*hv3.w;
        }
        // split-K reduction over kg lanes (bits 0-1 of lane id)
#pragma unroll
        for (int c = 0; c < 4; c++)
#pragma unroll
            for (int q = 0; q < 4; q++) {
                float v = acc[c][q];
                v += __shfl_xor_sync(0xFFFFFFFFu, v, 1);
                v += __shfl_xor_sync(0xFFFFFFFFu, v, 2);
                acc[c][q] = v;
            }
        if (kg == 0) {
#pragma unroll
            for (int c = 0; c < 4; c++)
#pragma unroll
                for (int q = 0; q < 4; q++)
                    part[c][cg][bgr * 4 + q] = acc[c][q];
        }
        __syncthreads();
        {
            float gi = part[0][j2][bl] + xg0;
            float gf = part[1][j2][bl] + xg1;
            float g_ = part[2][j2][bl] + xg2;
            float go = part[3][j2][bl] + xg3;
            creg = sigf(gf) * creg + sigf(gi) * tanf_(g_);
            float h = sigf(go) * tanf_(creg);
            hnext[(d * 64 + b) * 256 + jg] = h;
            size_t oidx = (size_t)(b * Ssz + s) * 512 + d * 256 + jg;
            if (out) out[oidx] = h;
            outh[oidx] = __float2half(h);
        }
        // prefetch next step's gate inputs before the barrier
        if (t + 1 < Ssz) {
            int sn = (d == 0) ? (t + 1) : (Ssz - 2 - t);
            const float* xr2 = xW + (size_t)(b * Ssz + sn) * 2048 + d * 1024;
            xg0 = xr2[jg]; xg1 = xr2[256 + jg]; xg2 = xr2[512 + jg]; xg3 = xr2[768 + jg];
        }
        group_barrier(grp, 8);
    }
}

// ---------------- persistent decoder: pair-split phase A (R14 proven) ----------------
#define DEC_DSM (163840 + 20480)
__global__ __launch_bounds__(256) void decoder_all(
    const int* __restrict__ trg, const int* __restrict__ tfmask,
    const float* __restrict__ enc, const __half* __restrict__ encWaH,
    const __half* __restrict__ Wa1TH, const float* __restrict__ ba,
    const float* __restrict__ vvec, const float* __restrict__ dWT4,
    const float* __restrict__ db, const float* __restrict__ demb,
    const float* __restrict__ Wfc, const float* __restrict__ bfc,
    float* __restrict__ xin, float* __restrict__ hid,
    float* __restrict__ hc, __half* __restrict__ hcH,
    float* __restrict__ scg, float* __restrict__ ctxp)
{
    extern __shared__ char dsm[];
    float4* dws = (float4*)dsm;                   // [160 k4][64 gj]
    float4* xs4 = (float4*)(dsm + 163840);        // [8 b][160 k4]
    __shared__ float hsm_[256], hwa_[256], vs_[256], sc_[128];
    __shared__ float redm_, reds_;
    __shared__ int tok_;
    __shared__ float partB[4][16][8];
    __shared__ float ax_[768];
    __shared__ float abv_[256];
    __shared__ int abi_[256];

    int bid = blockIdx.x, tid = threadIdx.x;
    int jcB = bid & 15, bgB = bid >> 4;
    int b = bid & 63, sh = bid >> 6;              // pair role: sh=0 primary, 1 helper

    vs_[tid] = vvec[tid];
    {
        const float4* dW4 = (const float4*)dWT4;
        for (int i2 = tid; i2 < 160 * 64; i2 += 256) {
            int k4 = i2 >> 6, gj2 = i2 & 63;
            int g = gj2 >> 4, jj = gj2 & 15;
            dws[i2] = dW4[(size_t)k4 * 1024 + g * 256 + jcB * 16 + jj];
        }
    }
    dec_barrier(bid);

    for (int st = 0; st < Tsz - 1; st++) {
        // ===== phase A: pair (b, b+64), s-range split =====
        if (st == 0) hsm_[tid] = enc[((size_t)b * Ssz + (Ssz - 1)) * 512 + tid];
        else         hsm_[tid] = __ldcg(&hid[b * 256 + tid]);

        if (sh == 0) {
            if (st == 0) {
                if (tid == 0) tok_ = trg[b * Tsz];
            } else if (tfmask[st] != 0) {
                if (tid == 0) tok_ = trg[b * Tsz + st];
            } else {
                const float* hcp = hc + ((size_t)(st - 1) * Bsz + b) * 768;
                for (int i = tid; i < 768; i += 256) ax_[i] = __ldcg(&hcp[i]);
                __syncthreads();
                float best = -1e30f; int bix = 0;
                for (int v0 = tid; v0 < Vsz; v0 += 256) {
                    float s = bfc[v0];
                    const float* wr = Wfc + (size_t)v0 * 768;
                    for (int k = 0; k < 768; k++) s += ax_[k] * wr[k];
                    if (s > best) { best = s; bix = v0; }
                }
                abv_[tid] = best; abi_[tid] = bix;
                __syncthreads();
                for (int off = 128; off; off >>= 1) {
                    if (tid < off) {
                        if (abv_[tid + off] > abv_[tid] ||
                            (abv_[tid + off] == abv_[tid] && abi_[tid + off] < abi_[tid])) {
                            abv_[tid] = abv_[tid + off];
                            abi_[tid] = abi_[tid + off];
                        }
                    }
                    __syncthreads();
                }
                if (tid == 0) tok_ = abi_[0];
            }
        }
        __syncthreads();
        if (sh == 0 && tid < 128) xin[b * 640 + tid] = demb[(size_t)tok_ * 128 + tid];

        // hWa (both blocks, full, fp16 weights)
        {
            float acc = ba[tid];
#pragma unroll 16
            for (int k = 0; k < 256; k++)
                acc += hsm_[k] * __half2float(Wa1TH[k * 256 + tid]);
            hwa_[tid] = acc;
        }
        __syncthreads();

        // energies for own 64-s half -> global scores
        {
            int w = tid >> 5, l = tid & 31;
#pragma unroll
            for (int i = 0; i < 8; i++) {
                int s = sh * 64 + w * 8 + i;
                const __half* ep = encWaH + ((size_t)b * Ssz + s) * 256;
                float a2 = 0.f;
#pragma unroll
                for (int q = 0; q < 8; q++) {
                    int h = l + q * 32;
                    a2 += tanf_(hwa_[h] + __half2float(ep[h])) * vs_[h];
                }
#pragma unroll
                for (int o = 16; o; o >>= 1) a2 += __shfl_xor_sync(0xFFFFFFFFu, a2, o);
                if (l == 0) scg[b * 128 + s] = a2;
            }
        }
        group_barrier(64 + b, 2);                 // pair exchange: scores

        if (tid < 128) sc_[tid] = __ldcg(&scg[b * 128 + tid]);
        __syncthreads();
        if (tid < 32) {
            float m = fmaxf(fmaxf(sc_[tid], sc_[tid + 32]),
                            fmaxf(sc_[tid + 64], sc_[tid + 96]));
#pragma unroll
            for (int o = 16; o; o >>= 1) m = fmaxf(m, __shfl_xor_sync(0xFFFFFFFFu, m, o));
            if (tid == 0) redm_ = m;
        }
        __syncthreads();
        float mx = redm_;
        if (tid < 128) sc_[tid] = __expf(sc_[tid] - mx);
        __syncthreads();
        if (tid < 32) {
            float s_ = sc_[tid] + sc_[tid + 32] + sc_[tid + 64] + sc_[tid + 96];
#pragma unroll
            for (int o = 16; o; o >>= 1) s_ += __shfl_xor_sync(0xFFFFFFFFu, s_, o);
            if (tid == 0) reds_ = __fdividef(1.f, s_);
        }
        __syncthreads();
        {
            float inv = reds_;
            float c0 = 0.f, c1 = 0.f;
            const float* eb = enc + (size_t)b * Ssz * 512 + (size_t)sh * 64 * 512;
#pragma unroll 8
            for (int s = 0; s < 64; s++) {
                float a = sc_[sh * 64 + s] * inv;
                c0 += a * eb[s * 512 + tid];
                c1 += a * eb[s * 512 + 256 + tid];
            }
            if (sh == 1) {
                ctxp[b * 512 + tid]       = c0;
                ctxp[b * 512 + 256 + tid] = c1;
            }
            group_barrier(64 + b, 2);             // pair exchange: partial context
            if (sh == 0) {
                c0 += __ldcg(&ctxp[b * 512 + tid]);
                c1 += __ldcg(&ctxp[b * 512 + 256 + tid]);
                xin[b * 640 + 128 + tid] = c0;
                xin[b * 640 + 384 + tid] = c1;
                size_t hcb = ((size_t)st * Bsz + b) * 768;
                hc[hcb + 256 + tid] = c0;
                hc[hcb + 512 + tid] = c1;
                hcH[hcb + 256 + tid] = __float2half(c0);
                hcH[hcb + 512 + tid] = __float2half(c1);
            }
        }
        dec_barrier(bid);

        // ===== phase B: gates, all 128 blocks =====
        {
            for (int i2 = tid; i2 < 8 * 160; i2 += 256) {
                int bi = i2 / 160, k4 = i2 - bi * 160;
                xs4[i2] = __ldcg((const float4*)(xin +
                               (size_t)(bgB * 8 + bi) * 640) + k4);
            }
            __syncthreads();
            int g = tid >> 6, jj = (tid >> 2) & 15, bq = tid & 3;
            float s0 = 0.f, s1 = 0.f;
            const float4* xa = xs4 + (bq * 2) * 160;
            const float4* xb = xs4 + (bq * 2 + 1) * 160;
            const float4* wp = dws + (g * 16 + jj);
#pragma unroll 4
            for (int k4 = 0; k4 < 160; k4++) {
                float4 w = wp[k4 * 64];
                float4 xA = xa[k4], xB = xb[k4];
                s0 += w.x * xA.x + w.y * xA.y + w.z * xA.z + w.w * xA.w;
                s1 += w.x * xB.x + w.y * xB.y + w.z * xB.z + w.w * xB.w;
            }
            partB[g][jj][bq * 2]     = s0;
            partB[g][jj][bq * 2 + 1] = s1;
            __syncthreads();
            if (tid < 128) {
                int jjf = tid >> 3, blf = tid & 7;
                int jgf = jcB * 16 + jjf, bbf = bgB * 8 + blf;
                float gi = partB[0][jjf][blf] + db[jgf];
                float g2 = partB[2][jjf][blf] + db[512 + jgf];
                float go = partB[3][jjf][blf] + db[768 + jgf];
                float cc = sigf(gi) * tanf_(g2);
                float hh = sigf(go) * tanf_(cc);
                hid[bbf * 256 + jgf] = hh;
                size_t hci = ((size_t)st * Bsz + bbf) * 768 + jgf;
                hc[hci] = hh;
                hcH[hci] = __float2half(hh);
            }
        }
        dec_barrier(bid);
    }
}

__global__ void zero_t0(float* __restrict__ out) {
    int b = blockIdx.x;
    int v = blockIdx.y * 256 + threadIdx.x;
    if (v < Vsz) out[(size_t)b * Tsz * Vsz + v] = 0.f;
}

// ---------------- host launch ----------------
static float* symaddr(const void* sym) {
    void* p = nullptr;
    cudaGetSymbolAddress(&p, sym);
    return (float*)p;
}
static __half* symaddrh(const void* sym) {
    void* p = nullptr;
    cudaGetSymbolAddress(&p, sym);
    return (__half*)p;
}

extern "C" void kernel_launch(void* const* d_in, const int* in_sizes, int n_in,
                              void* d_out, int out_size) {
    const int*   src     = (const int*)d_in[0];
    const int*   trg     = (const int*)d_in[1];
    const int*   tfmask  = (const int*)d_in[2];
    const float* enc_emb = (const float*)d_in[3];
    const float* e1f_Wih = (const float*)d_in[4];
    const float* e1f_Whh = (const float*)d_in[5];
    const float* e1f_b   = (const float*)d_in[6];
    const float* e1b_Wih = (const float*)d_in[7];
    const float* e1b_Whh = (const float*)d_in[8];
    const float* e1b_b   = (const float*)d_in[9];
    const float* e2f_Wih = (const float*)d_in[10];
    const float* e2f_Whh = (const float*)d_in[11];
    const float* e2f_b   = (const float*)d_in[12];
    const float* e2b_Wih = (const float*)d_in[13];
    const float* e2b_Whh = (const float*)d_in[14];
    const float* e2b_b   = (const float*)d_in[15];
    const float* dec_emb = (const float*)d_in[16];
    const float* Wa      = (const float*)d_in[17];
    const float* ba      = (const float*)d_in[18];
    const float* vvec    = (const float*)d_in[19];
    const float* dWih    = (const float*)d_in[20];
    const float* db      = (const float*)d_in[21];
    const float* Wfc     = (const float*)d_in[22];
    const float* bfc     = (const float*)d_in[23];
    float* out = (float*)d_out;

    float* p_xW    = symaddr(g_xW);
    float* p_enc   = symaddr(g_enc);
    float* p_b1c   = symaddr(g_b1c);
    float* p_b2c   = symaddr(g_b2c);
    float* p_WhhT4 = symaddr(g_WhhT4);
    float* p_dWT4  = symaddr(g_dWT4);
    float* p_h     = symaddr(g_h);
    float* p_hid   = symaddr(g_hid);
    float* p_xin   = symaddr(g_xin);
    float* p_hc    = symaddr(g_hc);
    float* p_scg   = symaddr(g_scg);
    float* p_ctxp  = symaddr(g_ctxp);

    __half* p_Ah     = symaddrh(g_Ah);
    __half* p_hcH    = symaddrh(g_hcH);
    __half* p_encWaH = symaddrh(g_encWaH);
    __half* p_Wa1TH  = symaddrh(g_Wa1TH);
    __half* p_B1hi = symaddrh(g_B1hi), * p_B1lo = symaddrh(g_B1lo);
    __half* p_B2hi = symaddrh(g_B2hi), * p_B2lo = symaddrh(g_B2lo);
    __half* p_BWahi = symaddrh(g_BWahi), * p_BWalo = symaddrh(g_BWalo);
    __half* p_Bfchi = symaddrh(g_Bfchi), * p_Bfclo = symaddrh(g_Bfclo);

    cudaFuncSetAttribute(gemm_tc, cudaFuncAttributeMaxDynamicSharedMemorySize, TCSM);
    cudaFuncSetAttribute(lstm_layer, cudaFuncAttributeMaxDynamicSharedMemorySize, LSTM_DSM);
    cudaFuncSetAttribute(decoder_all, cudaFuncAttributeMaxDynamicSharedMemorySize, DEC_DSM);

    auto nb = [](int n) { return (n + 255) / 256; };

    // [1] fused prep
    const int PREP_N = 65536 + 4 * 262144 + 655360 + 1024 + 1024 + 49152 + 49152
                     + 131072 + 131072 + 524288 + 524288 + 131072 + VPAD * 768;
    prep_fused<<<nb(PREP_N), 256>>>(
        Wa, e1f_Whh, e1b_Whh, e2f_Whh, e2b_Whh, dWih,
        e1f_b, e1b_b, e2f_b, e2b_b,
        e1f_Wih, e1b_Wih, e2f_Wih, e2b_Wih, Wfc,
        p_Wa1TH, p_WhhT4, p_dWT4, p_b1c, p_b2c,
        p_hc + (size_t)4032 * 768, p_hcH + (size_t)4032 * 768,
        p_B1hi, p_B1lo, p_B2hi, p_B2lo, p_BWahi, p_BWalo, p_Bfchi, p_Bfclo);
    // [2] embed + fp16 convert fused
    emb_half<<<Bsz * Ssz, Esz>>>(src, enc_emb, p_Ah);
    // [3] layer-1 GEMM
    gemm_tc<<<dim3(64, 16), 256, TCSM>>>(p_Ah, p_B1hi, p_B1lo,
                                         p_b1c, p_xW, 8192, 2048, 128, 0);
    // [4] layer-1 recurrence (re-tiled inner loop)
    lstm_layer<<<128, 256, LSTM_DSM>>>(p_xW, p_WhhT4, p_h, nullptr, p_Ah);
    // [5] layer-2 GEMM
    gemm_tc<<<dim3(64, 16), 256, TCSM>>>(p_Ah, p_B2hi, p_B2lo,
                                         p_b2c, p_xW, 8192, 2048, 512, 0);
    // [6] layer-2 recurrence
    lstm_layer<<<128, 256, LSTM_DSM>>>(p_xW, p_WhhT4 + 2 * 262144, p_h, p_enc, p_Ah);
    // [7] attention precompute GEMM -> fp16 encWa
    gemm_tc<<<dim3(64, 2), 256, TCSM>>>(p_Ah, p_BWahi, p_BWalo,
                                        nullptr, (float*)p_encWaH, 8192, 256, 512, 2);
    // [8] persistent decoder (pair-split phase A, fp32 enc context)
    decoder_all<<<128, 256, DEC_DSM>>>(trg, tfmask, p_enc, p_encWaH, p_Wa1TH,
                                       ba, vvec, p_dWT4, db, dec_emb, Wfc, bfc,
                                       p_xin, p_hid, p_hc, p_hcH, p_scg, p_ctxp);
    // [9] final projection (scatter into out)
    gemm_tc<<<dim3(32, 79), 256, TCSM>>>(p_hcH, p_Bfchi, p_Bfclo,
                                         bfc, out, 4032, Vsz, 768, 1);
    // [10] zero t=0 outputs
    zero_t0<<<dim3(Bsz, (Vsz + 255) / 256), 256>>>(out);
}